// round 6
// baseline (speedup 1.0000x reference)
#include <cuda_runtime.h>
#include <math.h>

// Problem dims (fixed by the reference)
#define Bb   64
#define Tt   2048
#define Ee   256
#define Hh   256
#define G3   768      // 3*H

// GEMM tiling
#define TM   128
#define TN   128
#define TKK  16
#define NKT  (Ee / TKK)   // 16 k-tiles

// Segmented scan
#define NSEG 16
#define TSEG (Tt / NSEG)  // 128

// Scratch: z,f gates [T*B, H]; per-segment affine composition (A, B)
__device__ float g_z[(size_t)Tt * Bb * Hh];
__device__ float g_f[(size_t)Tt * Bb * Hh];
__device__ float g_A [NSEG * Bb * Hh];
__device__ float g_Bc[NSEG * Bb * Hh];

// ---- packed fp32x2 FMA helpers (FFMA2 — 2x fp32 throughput, PTX-only) ----
__device__ __forceinline__ void ffma2(unsigned long long& d,
                                      unsigned long long a,
                                      unsigned long long b) {
    asm("fma.rn.f32x2 %0, %1, %2, %0;" : "+l"(d) : "l"(a), "l"(b));
}
__device__ __forceinline__ unsigned long long pack2(float lo, float hi) {
    unsigned long long r;
    asm("mov.b64 %0, {%1, %2};" : "=l"(r) : "f"(lo), "f"(hi));
    return r;
}
__device__ __forceinline__ void unpack2(unsigned long long v, float& lo, float& hi) {
    asm("mov.b64 {%0, %1}, %2;" : "=f"(lo), "=f"(hi) : "l"(v));
}

// =====================================================================
// Kernel 1: fused embedding-gather GEMM + gate activation.
//   Row r = t*B + b  (r in [0, 131072)), A[r,:] = emb[X[b,t], :]
//   Cols j in [0,512): j<256 -> z (tanh), j>=256 -> f (sigmoid)
//   Writes g_z[r*H + h], g_f[r*H + h].
// 128x128 tile, K-tile 16, double-buffered smem, 8x8 per thread via FFMA2.
// =====================================================================
__global__ __launch_bounds__(256, 2) void gemm_gates_kernel(
    const int* __restrict__ X, const float* __restrict__ emb,
    const float* __restrict__ W, const float* __restrict__ bias)
{
    __shared__ __align__(16) float As[2][TKK][TM];
    __shared__ __align__(16) float Ws[2][TKK][TN];
    __shared__ int sIdx[TM];

    const int tid = threadIdx.x;
    const int n0g = blockIdx.x * TN;   // 0..383 step 128 (4 col blocks)
    const int r0  = blockIdx.y * TM;   // row block

    if (tid < TM) {
        int r = r0 + tid;
        // r = t*64 + b  ->  t = r>>6, b = r&63 ; X is [B,T]
        sIdx[tid] = X[(r & 63) * Tt + (r >> 6)];
    }
    __syncthreads();

    // ---- stage 0 load ----
    {
        const int k0 = 0;
        #pragma unroll
        for (int s = 0; s < 2; s++) {
            int id  = s * 256 + tid;
            int row = id & 127, c4 = id >> 7;          // A: 4 float4 per row
            float4 va = *(const float4*)(emb + (size_t)sIdx[row] * Ee + k0 + c4 * 4);
            As[0][c4 * 4 + 0][row] = va.x;
            As[0][c4 * 4 + 1][row] = va.y;
            As[0][c4 * 4 + 2][row] = va.z;
            As[0][c4 * 4 + 3][row] = va.w;
            int n4 = id & 31, kw = id >> 5;            // W: row-major [k][n]
            float4 vw = *(const float4*)(W + (size_t)(k0 + kw) * G3 + n0g + n4 * 4);
            *(float4*)&Ws[0][kw][n4 * 4] = vw;
        }
    }
    __syncthreads();

    unsigned long long acc2[8][4];
    #pragma unroll
    for (int i = 0; i < 8; i++)
        #pragma unroll
        for (int j = 0; j < 4; j++) acc2[i][j] = 0ULL;

    const int tx = tid & 15, ty = tid >> 4;
    const int m0 = ty * 8, n0 = tx * 8;

    float4 ra[2], rw[2];
    for (int kt = 0; kt < NKT; kt++) {
        const int cur = kt & 1, nxt = cur ^ 1;
        if (kt + 1 < NKT) {
            const int k0 = (kt + 1) * TKK;
            #pragma unroll
            for (int s = 0; s < 2; s++) {
                int id  = s * 256 + tid;
                int row = id & 127, c4 = id >> 7;
                ra[s] = *(const float4*)(emb + (size_t)sIdx[row] * Ee + k0 + c4 * 4);
                int n4 = id & 31, kw = id >> 5;
                rw[s] = *(const float4*)(W + (size_t)(k0 + kw) * G3 + n0g + n4 * 4);
            }
        }
        #pragma unroll
        for (int k = 0; k < TKK; k++) {
            float4 a0 = *(const float4*)&As[cur][k][m0];
            float4 a1 = *(const float4*)&As[cur][k][m0 + 4];
            float4 b0 = *(const float4*)&Ws[cur][k][n0];
            float4 b1 = *(const float4*)&Ws[cur][k][n0 + 4];
            unsigned long long bb0 = pack2(b0.x, b0.y);
            unsigned long long bb1 = pack2(b0.z, b0.w);
            unsigned long long bb2 = pack2(b1.x, b1.y);
            unsigned long long bb3 = pack2(b1.z, b1.w);
            float av[8] = {a0.x, a0.y, a0.z, a0.w, a1.x, a1.y, a1.z, a1.w};
            #pragma unroll
            for (int i = 0; i < 8; i++) {
                unsigned long long aa = pack2(av[i], av[i]);
                ffma2(acc2[i][0], aa, bb0);
                ffma2(acc2[i][1], aa, bb1);
                ffma2(acc2[i][2], aa, bb2);
                ffma2(acc2[i][3], aa, bb3);
            }
        }
        if (kt + 1 < NKT) {
            #pragma unroll
            for (int s = 0; s < 2; s++) {
                int id  = s * 256 + tid;
                int row = id & 127, c4 = id >> 7;
                As[nxt][c4 * 4 + 0][row] = ra[s].x;
                As[nxt][c4 * 4 + 1][row] = ra[s].y;
                As[nxt][c4 * 4 + 2][row] = ra[s].z;
                As[nxt][c4 * 4 + 3][row] = ra[s].w;
                int n4 = id & 31, kw = id >> 5;
                *(float4*)&Ws[nxt][kw][n4 * 4] = rw[s];
            }
        }
        __syncthreads();
    }

    // ---- epilogue: bias + activation + store ----
    const bool isZ = (n0g < 256);
    float* outp = isZ ? g_z : g_f;
    const int cbase = n0g + n0 - (isZ ? 0 : 256);
    #pragma unroll
    for (int i = 0; i < 8; i++) {
        size_t r = (size_t)(r0 + m0 + i);
        float v[8];
        #pragma unroll
        for (int jp = 0; jp < 4; jp++) {
            float lo, hi;
            unpack2(acc2[i][jp], lo, hi);
            v[2 * jp]     = lo + bias[n0g + n0 + 2 * jp];
            v[2 * jp + 1] = hi + bias[n0g + n0 + 2 * jp + 1];
        }
        #pragma unroll
        for (int j = 0; j < 8; j++) {
            float x = v[j];
            x = isZ ? tanhf(x) : (1.0f / (1.0f + expf(-x)));
            outp[r * Hh + cbase + j] = x;
        }
    }
}

// =====================================================================
// Kernel 2: segmented affine scan. Each thread owns (seg, b, h) and
// composes c' = f*c + (1-f)*z over TSEG steps into (A, B).
// =====================================================================
__global__ __launch_bounds__(256) void scan_seg_kernel()
{
    const int h   = threadIdx.x;
    const int b   = blockIdx.x & 63;
    const int seg = blockIdx.x >> 6;
    const size_t base = (size_t)b * Hh + h;

    float A = 1.0f, Bc = 0.0f;
    const int t0 = seg * TSEG;
    #pragma unroll 4
    for (int t = t0; t < t0 + TSEG; t++) {
        size_t off = (size_t)t * (Bb * Hh) + base;
        float f = g_f[off];
        float z = g_z[off];
        A  = A * f;
        Bc = f * Bc + (1.0f - f) * z;
    }
    g_A [(seg * Bb + b) * Hh + h] = A;
    g_Bc[(seg * Bb + b) * Hh + h] = Bc;
}

// =====================================================================
// Kernel 3: combine segments -> c_T ; compute o at t=T-1 ; h = o*c ;
// out[b] = h . W_out + b_out.  One block per batch, thread = channel h.
// =====================================================================
__global__ __launch_bounds__(256) void finalize_kernel(
    const int* __restrict__ X, const float* __restrict__ emb,
    const float* __restrict__ W, const float* __restrict__ bias,
    const float* __restrict__ c0, const float* __restrict__ W_out,
    const float* __restrict__ b_out, float* __restrict__ out)
{
    const int b = blockIdx.x;
    const int h = threadIdx.x;
    __shared__ float xs[Ee];
    __shared__ float red[256];

    // embedding row for last timestep
    const int idx = X[b * Tt + (Tt - 1)];
    xs[h] = emb[(size_t)idx * Ee + h];
    __syncthreads();

    // combine segment compositions (sequential over 16 segments)
    float c = c0[b * Hh + h];
    #pragma unroll
    for (int s = 0; s < NSEG; s++) {
        float A  = g_A [(s * Bb + b) * Hh + h];
        float Bc = g_Bc[(s * Bb + b) * Hh + h];
        c = A * c + Bc;
    }

    // o gate at t = T-1 : column (512 + h) of W
    float acc = bias[512 + h];
    #pragma unroll 8
    for (int e = 0; e < Ee; e++)
        acc += xs[e] * W[(size_t)e * G3 + 512 + h];
    float o = 1.0f / (1.0f + expf(-acc));

    red[h] = (o * c) * W_out[h];
    __syncthreads();
    for (int st = 128; st > 0; st >>= 1) {
        if (h < st) red[h] += red[h + st];
        __syncthreads();
    }
    if (h == 0) out[b] = red[0] + b_out[0];
}

// =====================================================================
extern "C" void kernel_launch(void* const* d_in, const int* in_sizes, int n_in,
                              void* d_out, int out_size)
{
    const int*   X     = (const int*)  d_in[0];
    const float* emb   = (const float*)d_in[1];
    const float* W     = (const float*)d_in[2];
    const float* bias  = (const float*)d_in[3];
    const float* c0    = (const float*)d_in[4];
    const float* W_out = (const float*)d_in[5];
    const float* b_out = (const float*)d_in[6];
    float* out = (float*)d_out;

    // GEMM over 512 needed columns: grid = (512/128 col blocks, 131072/128 row blocks)
    dim3 g1(4, (Bb * Tt) / TM);
    gemm_gates_kernel<<<g1, 256>>>(X, emb, W, bias);
    scan_seg_kernel<<<NSEG * Bb, 256>>>();
    finalize_kernel<<<Bb, 256>>>(X, emb, W, bias, c0, W_out, b_out, out);
}

// round 8
// speedup vs baseline: 2.2370x; 2.2370x over previous
#include <cuda_runtime.h>
#include <cuda_bf16.h>
#include <math.h>
#include <stdint.h>

// Problem dims (fixed by the reference)
#define Bb   64
#define Tt   2048
#define Ee   256
#define Hh   256
#define G3   768      // 3*H

// Segmented scan
#define NSEG 16
#define TSEG (Tt / NSEG)  // 128

// K chunking for the GEMM
#define CH   32
#define NCH  (Ee / CH)    // 8

// Scratch
__device__ float g_z[(size_t)Tt * Bb * Hh];
__device__ float g_f[(size_t)Tt * Bb * Hh];
__device__ float g_A [NSEG * Bb * Hh];
__device__ float g_Bc[NSEG * Bb * Hh];
// Pre-transposed, split-bf16 weights: Wt[j][e] = W[e][j], j in [0,512)
__device__ __nv_bfloat16 g_Wth[512 * 256];
__device__ __nv_bfloat16 g_Wtl[512 * 256];

// ---------------- helpers ----------------
__device__ __forceinline__ uint32_t smem_u32(const void* p) {
    uint32_t a;
    asm("{ .reg .u64 t; cvta.to.shared.u64 t, %1; cvt.u32.u64 %0, t; }"
        : "=r"(a) : "l"(p));
    return a;
}
__device__ __forceinline__ uint32_t pack_bf16x2(__nv_bfloat16 a, __nv_bfloat16 b) {
    uint16_t la = *(uint16_t*)&a, lb = *(uint16_t*)&b;
    return (uint32_t)la | ((uint32_t)lb << 16);
}
// m16n8k16 bf16 mma, fp32 accum (baseline sm_80+ instruction — works at compute_103)
__device__ __forceinline__ void mma16816(float* c, const uint32_t* a, const uint32_t* b) {
    asm volatile(
        "mma.sync.aligned.m16n8k16.row.col.f32.bf16.bf16.f32 "
        "{%0,%1,%2,%3}, {%4,%5,%6,%7}, {%8,%9}, {%0,%1,%2,%3};"
        : "+f"(c[0]), "+f"(c[1]), "+f"(c[2]), "+f"(c[3])
        : "r"(a[0]), "r"(a[1]), "r"(a[2]), "r"(a[3]), "r"(b[0]), "r"(b[1]));
}
__device__ __forceinline__ void cp_async16(uint32_t dst, const void* src) {
    asm volatile("cp.async.cg.shared.global [%0], [%1], 16;" :: "r"(dst), "l"(src));
}

// SMEM layout (dynamic):
//   [0,512)    sIdx (128 ints)
//   [512,1024) bias_s (128 floats)
//   [1024, +2*40960) two stages; each stage:
//     A_hi +0, A_lo +10240, W_hi +20480, W_lo +30720
//   plane = 128 rows x 80 bytes (32 bf16 data + 8 bf16 pad -> conflict-free)
#define ROWB        80
#define PLANE_BYTES (128 * ROWB)       // 10240
#define A_HI_OFF    0
#define A_LO_OFF    10240
#define W_HI_OFF    20480
#define W_LO_OFF    30720
#define STAGE_BYTES 40960
#define SMEM_BYTES  (1024 + 2 * STAGE_BYTES)

__device__ __forceinline__ void store_split_row(char* stage, int row, int k, float4 v) {
    __nv_bfloat16 hx = __float2bfloat16(v.x);
    __nv_bfloat16 hy = __float2bfloat16(v.y);
    __nv_bfloat16 hz = __float2bfloat16(v.z);
    __nv_bfloat16 hw = __float2bfloat16(v.w);
    __nv_bfloat16 lx = __float2bfloat16(v.x - __bfloat162float(hx));
    __nv_bfloat16 ly = __float2bfloat16(v.y - __bfloat162float(hy));
    __nv_bfloat16 lz = __float2bfloat16(v.z - __bfloat162float(hz));
    __nv_bfloat16 lw = __float2bfloat16(v.w - __bfloat162float(hw));
    uint32_t off = (uint32_t)row * ROWB + (uint32_t)k * 2;
    *(uint32_t*)(stage + A_HI_OFF + off)     = pack_bf16x2(hx, hy);
    *(uint32_t*)(stage + A_HI_OFF + off + 4) = pack_bf16x2(hz, hw);
    *(uint32_t*)(stage + A_LO_OFF + off)     = pack_bf16x2(lx, ly);
    *(uint32_t*)(stage + A_LO_OFF + off + 4) = pack_bf16x2(lz, lw);
}

// =====================================================================
// Prep kernel: transpose + split-bf16 the needed 512 columns of W.
// =====================================================================
__global__ void prep_w_kernel(const float* __restrict__ W) {
    int j = blockIdx.x;       // gate column, 0..511
    int e = threadIdx.x;      // embedding dim, 0..255
    float w = W[(size_t)e * G3 + j];
    __nv_bfloat16 hi = __float2bfloat16(w);
    float lo = w - __bfloat162float(hi);
    g_Wth[j * 256 + e] = hi;
    g_Wtl[j * 256 + e] = __float2bfloat16(lo);
}

// =====================================================================
// Split-bf16 GEMM via mma.sync (HMMA) + fused gather + activation.
// CTA: 128 rows (r=t*64+b) x 128 gate cols. 8 warps, warp tile 64x32.
// 3 passes per k16: Ahi*Whi + Alo*Whi + Ahi*Wlo  (residual ~2^-16).
// =====================================================================
__global__ __launch_bounds__(256, 2)
void gemm_mma_kernel(const int* __restrict__ X, const float* __restrict__ emb,
                     const float* __restrict__ bias)
{
    extern __shared__ __align__(16) char smem[];
    const int tid  = threadIdx.x;
    const int wid  = tid >> 5, lane = tid & 31;
    const int g    = lane >> 2, tg = lane & 3;
    const int wm   = wid >> 2, wn = wid & 3;        // 2 x 4 warp grid
    const int n0g  = blockIdx.x * 128;              // 0,128,256,384
    const int r0   = blockIdx.y * 128;

    int*   sIdx   = (int*)smem;
    float* bias_s = (float*)(smem + 512);
    char*  planes = smem + 1024;
    const uint32_t planes_u32 = smem_u32(planes);

    if (tid < 128) {
        int r = r0 + tid;                  // r = t*64 + b
        sIdx[tid]   = X[(r & 63) * Tt + (r >> 6)];
        bias_s[tid] = bias[n0g + tid];
    }
    __syncthreads();

    float acc[4][4][4];
    #pragma unroll
    for (int mi = 0; mi < 4; mi++)
        #pragma unroll
        for (int ni = 0; ni < 4; ni++)
            #pragma unroll
            for (int c = 0; c < 4; c++) acc[mi][ni][c] = 0.0f;

    // ---- prologue: load stage 0 ----
    {
        const int k0 = 0;
        #pragma unroll
        for (int i = 0; i < 4; i++) {
            int id = i * 256 + tid;
            int row = id >> 3, f4 = id & 7;
            float4 v = *(const float4*)(emb + (size_t)sIdx[row] * Ee + k0 + f4 * 4);
            store_split_row(planes, row, f4 * 4, v);
        }
        #pragma unroll
        for (int i = 0; i < 4; i++) {
            int id = i * 256 + tid;
            int plane = id >> 9, id2 = id & 511;
            int row = id2 >> 2, u4 = id2 & 3;
            const __nv_bfloat16* src =
                (plane ? g_Wtl : g_Wth) + (size_t)(n0g + row) * Ee + k0 + u4 * 8;
            uint32_t dst = planes_u32 + (plane ? W_LO_OFF : W_HI_OFF)
                         + (uint32_t)row * ROWB + (uint32_t)u4 * 16;
            cp_async16(dst, src);
        }
        asm volatile("cp.async.commit_group;");
        asm volatile("cp.async.wait_group 0;");
    }
    __syncthreads();

    for (int ch = 0; ch < NCH; ch++) {
        const int cur = ch & 1, nxt = cur ^ 1;

        // prefetch next chunk: A into regs, W via cp.async straight to smem[nxt]
        float4 aPre[4];
        if (ch + 1 < NCH) {
            const int k0 = (ch + 1) * CH;
            #pragma unroll
            for (int i = 0; i < 4; i++) {
                int id = i * 256 + tid;
                int row = id >> 3, f4 = id & 7;
                aPre[i] = *(const float4*)(emb + (size_t)sIdx[row] * Ee + k0 + f4 * 4);
            }
            #pragma unroll
            for (int i = 0; i < 4; i++) {
                int id = i * 256 + tid;
                int plane = id >> 9, id2 = id & 511;
                int row = id2 >> 2, u4 = id2 & 3;
                const __nv_bfloat16* src =
                    (plane ? g_Wtl : g_Wth) + (size_t)(n0g + row) * Ee + k0 + u4 * 8;
                uint32_t dst = planes_u32 + (uint32_t)nxt * STAGE_BYTES
                             + (plane ? W_LO_OFF : W_HI_OFF)
                             + (uint32_t)row * ROWB + (uint32_t)u4 * 16;
                cp_async16(dst, src);
            }
            asm volatile("cp.async.commit_group;");
        }

        // ---- compute on current stage ----
        const char* base = planes + cur * STAGE_BYTES;
        #pragma unroll
        for (int k16 = 0; k16 < CH; k16 += 16) {
            #pragma unroll
            for (int pass = 0; pass < 3; pass++) {
                const char* ap = base + ((pass == 1) ? A_LO_OFF : A_HI_OFF);
                const char* bp = base + ((pass == 2) ? W_LO_OFF : W_HI_OFF);
                uint32_t afr[4][4];
                #pragma unroll
                for (int mi = 0; mi < 4; mi++) {
                    int off = (wm * 64 + mi * 16 + g) * ROWB + (k16 + tg * 2) * 2;
                    afr[mi][0] = *(const uint32_t*)(ap + off);
                    afr[mi][1] = *(const uint32_t*)(ap + off + 8 * ROWB);
                    afr[mi][2] = *(const uint32_t*)(ap + off + 16);
                    afr[mi][3] = *(const uint32_t*)(ap + off + 8 * ROWB + 16);
                }
                uint32_t bfr[4][2];
                #pragma unroll
                for (int ni = 0; ni < 4; ni++) {
                    int off = (wn * 32 + ni * 8 + g) * ROWB + (k16 + tg * 2) * 2;
                    bfr[ni][0] = *(const uint32_t*)(bp + off);
                    bfr[ni][1] = *(const uint32_t*)(bp + off + 16);
                }
                #pragma unroll
                for (int mi = 0; mi < 4; mi++)
                    #pragma unroll
                    for (int ni = 0; ni < 4; ni++)
                        mma16816(acc[mi][ni], afr[mi], bfr[ni]);
            }
        }

        // drain prefetch into smem[nxt]
        if (ch + 1 < NCH) {
            char* nb = planes + nxt * STAGE_BYTES;
            #pragma unroll
            for (int i = 0; i < 4; i++) {
                int id = i * 256 + tid;
                int row = id >> 3, f4 = id & 7;
                store_split_row(nb, row, f4 * 4, aPre[i]);
            }
            asm volatile("cp.async.wait_group 0;");
        }
        __syncthreads();
    }

    // ---- epilogue: bias + activation + store ----
    const bool isZ = (n0g < 256);
    float* outp = isZ ? g_z : g_f;
    const int cbase = isZ ? n0g : (n0g - 256);
    #pragma unroll
    for (int mi = 0; mi < 4; mi++) {
        #pragma unroll
        for (int ni = 0; ni < 4; ni++) {
            int lr = wm * 64 + mi * 16 + g;
            int lc = wn * 32 + ni * 8 + tg * 2;
            #pragma unroll
            for (int half = 0; half < 2; half++) {
                float v0 = acc[mi][ni][2 * half + 0] + bias_s[lc];
                float v1 = acc[mi][ni][2 * half + 1] + bias_s[lc + 1];
                float2 o;
                if (isZ) { o.x = tanhf(v0); o.y = tanhf(v1); }
                else {
                    o.x = 1.0f / (1.0f + expf(-v0));
                    o.y = 1.0f / (1.0f + expf(-v1));
                }
                size_t r = (size_t)(r0 + lr + half * 8);
                *(float2*)(outp + r * Hh + cbase + lc) = o;
            }
        }
    }
}

// =====================================================================
// Kernel 2: segmented affine scan.
// =====================================================================
__global__ __launch_bounds__(256) void scan_seg_kernel()
{
    const int h   = threadIdx.x;
    const int b   = blockIdx.x & 63;
    const int seg = blockIdx.x >> 6;
    const size_t base = (size_t)b * Hh + h;

    float A = 1.0f, Bc = 0.0f;
    const int t0 = seg * TSEG;
    #pragma unroll 4
    for (int t = t0; t < t0 + TSEG; t++) {
        size_t off = (size_t)t * (Bb * Hh) + base;
        float f = g_f[off];
        float z = g_z[off];
        A  = A * f;
        Bc = f * Bc + (1.0f - f) * z;
    }
    g_A [(seg * Bb + b) * Hh + h] = A;
    g_Bc[(seg * Bb + b) * Hh + h] = Bc;
}

// =====================================================================
// Kernel 3: combine segments, o-gate at t=T-1, output dot.
// =====================================================================
__global__ __launch_bounds__(256) void finalize_kernel(
    const int* __restrict__ X, const float* __restrict__ emb,
    const float* __restrict__ W, const float* __restrict__ bias,
    const float* __restrict__ c0, const float* __restrict__ W_out,
    const float* __restrict__ b_out, float* __restrict__ out)
{
    const int b = blockIdx.x;
    const int h = threadIdx.x;
    __shared__ float xs[Ee];
    __shared__ float red[256];

    const int idx = X[b * Tt + (Tt - 1)];
    xs[h] = emb[(size_t)idx * Ee + h];
    __syncthreads();

    float c = c0[b * Hh + h];
    #pragma unroll
    for (int s = 0; s < NSEG; s++) {
        float A  = g_A [(s * Bb + b) * Hh + h];
        float Bc = g_Bc[(s * Bb + b) * Hh + h];
        c = A * c + Bc;
    }

    float acc = bias[512 + h];
    #pragma unroll 8
    for (int e = 0; e < Ee; e++)
        acc += xs[e] * W[(size_t)e * G3 + 512 + h];
    float o = 1.0f / (1.0f + expf(-acc));

    red[h] = (o * c) * W_out[h];
    __syncthreads();
    for (int st = 128; st > 0; st >>= 1) {
        if (h < st) red[h] += red[h + st];
        __syncthreads();
    }
    if (h == 0) out[b] = red[0] + b_out[0];
}

// =====================================================================
extern "C" void kernel_launch(void* const* d_in, const int* in_sizes, int n_in,
                              void* d_out, int out_size)
{
    const int*   X     = (const int*)  d_in[0];
    const float* emb   = (const float*)d_in[1];
    const float* W     = (const float*)d_in[2];
    const float* bias  = (const float*)d_in[3];
    const float* c0    = (const float*)d_in[4];
    const float* W_out = (const float*)d_in[5];
    const float* b_out = (const float*)d_in[6];
    float* out = (float*)d_out;

    cudaFuncSetAttribute(gemm_mma_kernel,
                         cudaFuncAttributeMaxDynamicSharedMemorySize, SMEM_BYTES);

    prep_w_kernel<<<512, 256>>>(W);
    dim3 g1(4, (Bb * Tt) / 128);
    gemm_mma_kernel<<<g1, 256, SMEM_BYTES>>>(X, emb, bias);
    scan_seg_kernel<<<NSEG * Bb, 256>>>();
    finalize_kernel<<<Bb, 256>>>(X, emb, W, bias, c0, W_out, b_out, out);
}

// round 10
// speedup vs baseline: 2.4271x; 1.0850x over previous
#include <cuda_runtime.h>
#include <cuda_bf16.h>
#include <math.h>
#include <stdint.h>

// Problem dims (fixed by the reference)
#define Bb   64
#define Tt   2048
#define Ee   256
#define Hh   256
#define G3   768      // 3*H

// Segmented scan
#define NSEG 16
#define TSEG (Tt / NSEG)  // 128

// K chunking for the GEMM
#define CH   32
#define NCH  (Ee / CH)    // 8

// Scratch
__device__ float g_z[(size_t)Tt * Bb * Hh];
__device__ float g_f[(size_t)Tt * Bb * Hh];
__device__ float g_A [NSEG * Bb * Hh];
__device__ float g_Bc[NSEG * Bb * Hh];
__device__ float g_o [Bb * Hh];            // o-gate at t = T-1
// Pre-transposed, split-bf16 weights: Wt[j][e] = W[e][j], j in [0,512)
__device__ __nv_bfloat16 g_Wth[512 * 256];
__device__ __nv_bfloat16 g_Wtl[512 * 256];

// ---------------- helpers ----------------
__device__ __forceinline__ uint32_t smem_u32(const void* p) {
    uint32_t a;
    asm("{ .reg .u64 t; cvta.to.shared.u64 t, %1; cvt.u32.u64 %0, t; }"
        : "=r"(a) : "l"(p));
    return a;
}
__device__ __forceinline__ uint32_t pack_bf16x2(__nv_bfloat16 a, __nv_bfloat16 b) {
    uint16_t la = *(uint16_t*)&a, lb = *(uint16_t*)&b;
    return (uint32_t)la | ((uint32_t)lb << 16);
}
// m16n8k16 bf16 mma, fp32 accum (baseline sm_80+, OK at compute_103)
__device__ __forceinline__ void mma16816(float* c, const uint32_t* a, const uint32_t* b) {
    asm volatile(
        "mma.sync.aligned.m16n8k16.row.col.f32.bf16.bf16.f32 "
        "{%0,%1,%2,%3}, {%4,%5,%6,%7}, {%8,%9}, {%0,%1,%2,%3};"
        : "+f"(c[0]), "+f"(c[1]), "+f"(c[2]), "+f"(c[3])
        : "r"(a[0]), "r"(a[1]), "r"(a[2]), "r"(a[3]), "r"(b[0]), "r"(b[1]));
}
__device__ __forceinline__ void ldmx4(uint32_t* r, uint32_t addr) {
    asm volatile("ldmatrix.sync.aligned.m8n8.x4.shared.b16 {%0,%1,%2,%3}, [%4];"
                 : "=r"(r[0]), "=r"(r[1]), "=r"(r[2]), "=r"(r[3]) : "r"(addr));
}
__device__ __forceinline__ void cp_async16(uint32_t dst, const void* src) {
    asm volatile("cp.async.cg.shared.global [%0], [%1], 16;" :: "r"(dst), "l"(src));
}

// SMEM layout (dynamic):
//   [0,512)    sIdx (128 ints)
//   [512,1024) bias_s (128 floats)
//   [1024, +2*40960) two stages; each stage:
//     A_hi +0, A_lo +10240, W_hi +20480, W_lo +30720
//   plane = 128 rows x 80 bytes (32 bf16 data + 8 bf16 pad -> conflict-free)
#define ROWB        80
#define A_HI_OFF    0
#define A_LO_OFF    10240
#define W_HI_OFF    20480
#define W_LO_OFF    30720
#define STAGE_BYTES 40960
#define SMEM_BYTES  (1024 + 2 * STAGE_BYTES)

__device__ __forceinline__ void store_split_row(char* stage, int row, int k, float4 v) {
    __nv_bfloat16 hx = __float2bfloat16(v.x);
    __nv_bfloat16 hy = __float2bfloat16(v.y);
    __nv_bfloat16 hz = __float2bfloat16(v.z);
    __nv_bfloat16 hw = __float2bfloat16(v.w);
    __nv_bfloat16 lx = __float2bfloat16(v.x - __bfloat162float(hx));
    __nv_bfloat16 ly = __float2bfloat16(v.y - __bfloat162float(hy));
    __nv_bfloat16 lz = __float2bfloat16(v.z - __bfloat162float(hz));
    __nv_bfloat16 lw = __float2bfloat16(v.w - __bfloat162float(hw));
    uint32_t off = (uint32_t)row * ROWB + (uint32_t)k * 2;
    *(uint32_t*)(stage + A_HI_OFF + off)     = pack_bf16x2(hx, hy);
    *(uint32_t*)(stage + A_HI_OFF + off + 4) = pack_bf16x2(hz, hw);
    *(uint32_t*)(stage + A_LO_OFF + off)     = pack_bf16x2(lx, ly);
    *(uint32_t*)(stage + A_LO_OFF + off + 4) = pack_bf16x2(lz, lw);
}

// =====================================================================
// Prep kernel: transpose + split-bf16 the needed 512 columns of W.
// =====================================================================
__global__ void prep_w_kernel(const float* __restrict__ W) {
    int j = blockIdx.x;       // gate column, 0..511
    int e = threadIdx.x;      // embedding dim, 0..255
    float w = W[(size_t)e * G3 + j];
    __nv_bfloat16 hi = __float2bfloat16(w);
    float lo = w - __bfloat162float(hi);
    g_Wth[j * 256 + e] = hi;
    g_Wtl[j * 256 + e] = __float2bfloat16(lo);
}

// =====================================================================
// Split-bf16 GEMM via mma.sync + ldmatrix + fused gather + activation.
// CTA: 128 rows (r=t*64+b) x 128 gate cols. 8 warps, warp tile 64x32.
// Per k16: ldmatrix Ahi(4) Whi(2) Wlo(2) -> Ahi*Whi, Ahi*Wlo;
//          ldmatrix Alo(4, overwriting Ahi regs) -> Alo*Whi.
// =====================================================================
__global__ __launch_bounds__(256, 2)
void gemm_mma_kernel(const int* __restrict__ X, const float* __restrict__ emb,
                     const float* __restrict__ bias)
{
    extern __shared__ __align__(16) char smem[];
    const int tid  = threadIdx.x;
    const int wid  = tid >> 5, lane = tid & 31;
    const int g    = lane >> 2, tg = lane & 3;
    const int wm   = wid >> 2, wn = wid & 3;        // 2 x 4 warp grid
    const int n0g  = blockIdx.x * 128;              // 0,128,256,384
    const int r0   = blockIdx.y * 128;

    int*   sIdx   = (int*)smem;
    float* bias_s = (float*)(smem + 512);
    char*  planes = smem + 1024;
    const uint32_t planes_u32 = smem_u32(planes);

    // per-lane ldmatrix row offsets (A and B), see fragment mapping notes
    const int aRow = (lane & 7) | (lane & 8);          // 0..15
    const int aK8  = (lane >> 4) * 8;                  // 0 or 8
    const int bN   = (lane & 7) + ((lane & 16) >> 1);  // 0..15
    const int bK8  = (lane & 8);                       // 0 or 8
    const uint32_t aOff = (uint32_t)(wm * 64 + aRow) * ROWB + (uint32_t)aK8 * 2;
    const uint32_t bOff = (uint32_t)(wn * 32 + bN)  * ROWB + (uint32_t)bK8 * 2;

    if (tid < 128) {
        int r = r0 + tid;                  // r = t*64 + b
        sIdx[tid]   = X[(r & 63) * Tt + (r >> 6)];
        bias_s[tid] = bias[n0g + tid];
    }
    __syncthreads();

    float acc[4][4][4];
    #pragma unroll
    for (int mi = 0; mi < 4; mi++)
        #pragma unroll
        for (int ni = 0; ni < 4; ni++)
            #pragma unroll
            for (int c = 0; c < 4; c++) acc[mi][ni][c] = 0.0f;

    // ---- prologue: load stage 0 ----
    {
        #pragma unroll
        for (int i = 0; i < 4; i++) {
            int id = i * 256 + tid;
            int row = id >> 3, f4 = id & 7;
            float4 v = *(const float4*)(emb + (size_t)sIdx[row] * Ee + f4 * 4);
            store_split_row(planes, row, f4 * 4, v);
        }
        #pragma unroll
        for (int i = 0; i < 4; i++) {
            int id = i * 256 + tid;
            int plane = id >> 9, id2 = id & 511;
            int row = id2 >> 2, u4 = id2 & 3;
            const __nv_bfloat16* src =
                (plane ? g_Wtl : g_Wth) + (size_t)(n0g + row) * Ee + u4 * 8;
            uint32_t dst = planes_u32 + (plane ? W_LO_OFF : W_HI_OFF)
                         + (uint32_t)row * ROWB + (uint32_t)u4 * 16;
            cp_async16(dst, src);
        }
        asm volatile("cp.async.commit_group;");
        asm volatile("cp.async.wait_group 0;");
    }
    __syncthreads();

    for (int ch = 0; ch < NCH; ch++) {
        const int cur = ch & 1, nxt = cur ^ 1;

        // prefetch next chunk: A into regs, W via cp.async straight to smem[nxt]
        float4 aPre[4];
        if (ch + 1 < NCH) {
            const int k0 = (ch + 1) * CH;
            #pragma unroll
            for (int i = 0; i < 4; i++) {
                int id = i * 256 + tid;
                int row = id >> 3, f4 = id & 7;
                aPre[i] = *(const float4*)(emb + (size_t)sIdx[row] * Ee + k0 + f4 * 4);
            }
            #pragma unroll
            for (int i = 0; i < 4; i++) {
                int id = i * 256 + tid;
                int plane = id >> 9, id2 = id & 511;
                int row = id2 >> 2, u4 = id2 & 3;
                const __nv_bfloat16* src =
                    (plane ? g_Wtl : g_Wth) + (size_t)(n0g + row) * Ee + k0 + u4 * 8;
                uint32_t dst = planes_u32 + (uint32_t)nxt * STAGE_BYTES
                             + (plane ? W_LO_OFF : W_HI_OFF)
                             + (uint32_t)row * ROWB + (uint32_t)u4 * 16;
                cp_async16(dst, src);
            }
            asm volatile("cp.async.commit_group;");
        }

        // ---- compute on current stage ----
        const uint32_t sb = planes_u32 + (uint32_t)cur * STAGE_BYTES;
        #pragma unroll
        for (int k16 = 0; k16 < CH; k16 += 16) {
            const uint32_t kb = (uint32_t)k16 * 2;
            uint32_t afr[4][4], bhi[2][4], blo[2][4];
            #pragma unroll
            for (int nn = 0; nn < 2; nn++) {
                ldmx4(bhi[nn], sb + W_HI_OFF + bOff + (uint32_t)nn * 16 * ROWB + kb);
                ldmx4(blo[nn], sb + W_LO_OFF + bOff + (uint32_t)nn * 16 * ROWB + kb);
            }
            #pragma unroll
            for (int mi = 0; mi < 4; mi++)
                ldmx4(afr[mi], sb + A_HI_OFF + aOff + (uint32_t)mi * 16 * ROWB + kb);
            // Ahi*Whi  +  Ahi*Wlo
            #pragma unroll
            for (int mi = 0; mi < 4; mi++)
                #pragma unroll
                for (int ni = 0; ni < 4; ni++) {
                    mma16816(acc[mi][ni], afr[mi], &bhi[ni >> 1][(ni & 1) * 2]);
                    mma16816(acc[mi][ni], afr[mi], &blo[ni >> 1][(ni & 1) * 2]);
                }
            // Alo*Whi (overwrite A regs)
            #pragma unroll
            for (int mi = 0; mi < 4; mi++)
                ldmx4(afr[mi], sb + A_LO_OFF + aOff + (uint32_t)mi * 16 * ROWB + kb);
            #pragma unroll
            for (int mi = 0; mi < 4; mi++)
                #pragma unroll
                for (int ni = 0; ni < 4; ni++)
                    mma16816(acc[mi][ni], afr[mi], &bhi[ni >> 1][(ni & 1) * 2]);
        }

        // drain prefetch into smem[nxt]
        if (ch + 1 < NCH) {
            char* nb = planes + nxt * STAGE_BYTES;
            #pragma unroll
            for (int i = 0; i < 4; i++) {
                int id = i * 256 + tid;
                int row = id >> 3, f4 = id & 7;
                store_split_row(nb, row, f4 * 4, aPre[i]);
            }
            asm volatile("cp.async.wait_group 0;");
        }
        __syncthreads();
    }

    // ---- epilogue: bias + activation + store ----
    const bool isZ = (n0g < 256);
    float* outp = isZ ? g_z : g_f;
    const int cbase = isZ ? n0g : (n0g - 256);
    #pragma unroll
    for (int mi = 0; mi < 4; mi++) {
        #pragma unroll
        for (int ni = 0; ni < 4; ni++) {
            int lr = wm * 64 + mi * 16 + g;
            int lc = wn * 32 + ni * 8 + tg * 2;
            #pragma unroll
            for (int half = 0; half < 2; half++) {
                float v0 = acc[mi][ni][2 * half + 0] + bias_s[lc];
                float v1 = acc[mi][ni][2 * half + 1] + bias_s[lc + 1];
                float2 o;
                if (isZ) { o.x = tanhf(v0); o.y = tanhf(v1); }
                else {
                    o.x = 1.0f / (1.0f + expf(-v0));
                    o.y = 1.0f / (1.0f + expf(-v1));
                }
                size_t r = (size_t)(r0 + lr + half * 8);
                *(float2*)(outp + r * Hh + cbase + lc) = o;
            }
        }
    }
}

// =====================================================================
// Kernel 2: segmented affine scan + fused o-gate GEMV (extra 64 blocks).
// =====================================================================
__global__ __launch_bounds__(256) void scan_seg_kernel(
    const int* __restrict__ X, const float* __restrict__ emb,
    const float* __restrict__ W, const float* __restrict__ bias)
{
    if (blockIdx.x < NSEG * Bb) {
        const int h   = threadIdx.x;
        const int b   = blockIdx.x & 63;
        const int seg = blockIdx.x >> 6;
        const size_t base = (size_t)b * Hh + h;

        float A = 1.0f, Bc = 0.0f;
        const int t0 = seg * TSEG;
        #pragma unroll 4
        for (int t = t0; t < t0 + TSEG; t++) {
            size_t off = (size_t)t * (Bb * Hh) + base;
            float f = g_f[off];
            float z = g_z[off];
            A  = A * f;
            Bc = f * Bc + (1.0f - f) * z;
        }
        g_A [(seg * Bb + b) * Hh + h] = A;
        g_Bc[(seg * Bb + b) * Hh + h] = Bc;
    } else {
        // o-gate at t = T-1 for batch b (independent of GEMM outputs)
        const int b = blockIdx.x - NSEG * Bb;
        const int h = threadIdx.x;
        __shared__ float xs[Ee];
        const int idx = X[b * Tt + (Tt - 1)];
        xs[h] = emb[(size_t)idx * Ee + h];
        __syncthreads();
        float acc = bias[512 + h];
        #pragma unroll 8
        for (int e = 0; e < Ee; e++)
            acc += xs[e] * W[(size_t)e * G3 + 512 + h];
        g_o[b * Hh + h] = 1.0f / (1.0f + expf(-acc));
    }
}

// =====================================================================
// Kernel 3: combine segments -> c_T ; out[b] = (o*c) . W_out + b_out.
// =====================================================================
__global__ __launch_bounds__(256) void finalize_kernel(
    const float* __restrict__ c0, const float* __restrict__ W_out,
    const float* __restrict__ b_out, float* __restrict__ out)
{
    const int b = blockIdx.x;
    const int h = threadIdx.x;
    __shared__ float red[256];

    float c = c0[b * Hh + h];
    #pragma unroll
    for (int s = 0; s < NSEG; s++) {
        float A  = g_A [(s * Bb + b) * Hh + h];
        float Bc = g_Bc[(s * Bb + b) * Hh + h];
        c = A * c + Bc;
    }

    red[h] = (g_o[b * Hh + h] * c) * W_out[h];
    __syncthreads();
    for (int st = 128; st > 0; st >>= 1) {
        if (h < st) red[h] += red[h + st];
        __syncthreads();
    }
    if (h == 0) out[b] = red[0] + b_out[0];
}

// =====================================================================
extern "C" void kernel_launch(void* const* d_in, const int* in_sizes, int n_in,
                              void* d_out, int out_size)
{
    const int*   X     = (const int*)  d_in[0];
    const float* emb   = (const float*)d_in[1];
    const float* W     = (const float*)d_in[2];
    const float* bias  = (const float*)d_in[3];
    const float* c0    = (const float*)d_in[4];
    const float* W_out = (const float*)d_in[5];
    const float* b_out = (const float*)d_in[6];
    float* out = (float*)d_out;

    cudaFuncSetAttribute(gemm_mma_kernel,
                         cudaFuncAttributeMaxDynamicSharedMemorySize, SMEM_BYTES);

    prep_w_kernel<<<512, 256>>>(W);
    dim3 g1(4, (Bb * Tt) / 128);
    gemm_mma_kernel<<<g1, 256, SMEM_BYTES>>>(X, emb, bias);
    scan_seg_kernel<<<NSEG * Bb + Bb, 256>>>(X, emb, W, bias);
    finalize_kernel<<<Bb, 256>>>(c0, W_out, b_out, out);
}

// round 11
// speedup vs baseline: 2.6685x; 1.0995x over previous
#include <cuda_runtime.h>
#include <cuda_bf16.h>
#include <math.h>
#include <stdint.h>

// Problem dims (fixed by the reference)
#define Bb   64
#define Tt   2048
#define Ee   256
#define Hh   256
#define G3   768      // 3*H

// Segments: one GEMM row-block (128 rows) == one segment of 128 timesteps
#define NSEG 16
#define TSEG (Tt / NSEG)  // 128

// K chunking for the GEMM
#define CH   32
#define NCH  (Ee / CH)    // 8

// Scratch: per-segment affine composition, o-gate
__device__ float g_A [NSEG * Bb * Hh];
__device__ float g_Bc[NSEG * Bb * Hh];
__device__ float g_o [Bb * Hh];
// Pre-transposed, split-bf16, COLUMN-REMAPPED weights:
//   dest col j' = cb*128 + c ; src gate col = (c<64)? cb*64+c : 256+cb*64+(c-64)
__device__ __nv_bfloat16 g_Wth[512 * 256];
__device__ __nv_bfloat16 g_Wtl[512 * 256];

// ---------------- helpers ----------------
__device__ __forceinline__ uint32_t smem_u32(const void* p) {
    uint32_t a;
    asm("{ .reg .u64 t; cvta.to.shared.u64 t, %1; cvt.u32.u64 %0, t; }"
        : "=r"(a) : "l"(p));
    return a;
}
__device__ __forceinline__ uint32_t pack_bf16x2(__nv_bfloat16 a, __nv_bfloat16 b) {
    uint16_t la = *(uint16_t*)&a, lb = *(uint16_t*)&b;
    return (uint32_t)la | ((uint32_t)lb << 16);
}
__device__ __forceinline__ void mma16816(float* c, const uint32_t* a, const uint32_t* b) {
    asm volatile(
        "mma.sync.aligned.m16n8k16.row.col.f32.bf16.bf16.f32 "
        "{%0,%1,%2,%3}, {%4,%5,%6,%7}, {%8,%9}, {%0,%1,%2,%3};"
        : "+f"(c[0]), "+f"(c[1]), "+f"(c[2]), "+f"(c[3])
        : "r"(a[0]), "r"(a[1]), "r"(a[2]), "r"(a[3]), "r"(b[0]), "r"(b[1]));
}
__device__ __forceinline__ void ldmx4(uint32_t* r, uint32_t addr) {
    asm volatile("ldmatrix.sync.aligned.m8n8.x4.shared.b16 {%0,%1,%2,%3}, [%4];"
                 : "=r"(r[0]), "=r"(r[1]), "=r"(r[2]), "=r"(r[3]) : "r"(addr));
}
__device__ __forceinline__ void cp_async16(uint32_t dst, const void* src) {
    asm volatile("cp.async.cg.shared.global [%0], [%1], 16;" :: "r"(dst), "l"(src));
}

// SMEM layout:
//   [0,512)    sIdx (128 ints)
//   [512,1024) bias_s (128 floats)
//   [1024, +2*40960) two pipeline stages (A_hi/A_lo/W_hi/W_lo planes, 80B rows)
// Epilogue reuses the stage area:
//   zPlane [128][68]f at +0, fPlane at +34816, partials (2*256 f) at +69632
#define ROWB        80
#define A_HI_OFF    0
#define A_LO_OFF    10240
#define W_HI_OFF    20480
#define W_LO_OFF    30720
#define STAGE_BYTES 40960
#define SMEM_BYTES  (1024 + 2 * STAGE_BYTES)
#define EP_F_OFF    34816          // 128*68*4
#define EP_PART_OFF 69632

__device__ __forceinline__ void store_split_row(char* stage, int row, int k, float4 v) {
    __nv_bfloat16 hx = __float2bfloat16(v.x);
    __nv_bfloat16 hy = __float2bfloat16(v.y);
    __nv_bfloat16 hz = __float2bfloat16(v.z);
    __nv_bfloat16 hw = __float2bfloat16(v.w);
    __nv_bfloat16 lx = __float2bfloat16(v.x - __bfloat162float(hx));
    __nv_bfloat16 ly = __float2bfloat16(v.y - __bfloat162float(hy));
    __nv_bfloat16 lz = __float2bfloat16(v.z - __bfloat162float(hz));
    __nv_bfloat16 lw = __float2bfloat16(v.w - __bfloat162float(hw));
    uint32_t off = (uint32_t)row * ROWB + (uint32_t)k * 2;
    *(uint32_t*)(stage + A_HI_OFF + off)     = pack_bf16x2(hx, hy);
    *(uint32_t*)(stage + A_HI_OFF + off + 4) = pack_bf16x2(hz, hw);
    *(uint32_t*)(stage + A_LO_OFF + off)     = pack_bf16x2(lx, ly);
    *(uint32_t*)(stage + A_LO_OFF + off + 4) = pack_bf16x2(lz, lw);
}

// =====================================================================
// Prep: transpose + split + column-remap W (blocks 0..511);
//       o-gate GEMV at t=T-1 (blocks 512..575).
// =====================================================================
__global__ void prep_kernel(const int* __restrict__ X, const float* __restrict__ emb,
                            const float* __restrict__ W, const float* __restrict__ bias)
{
    if (blockIdx.x < 512) {
        int jp = blockIdx.x;                  // destination column
        int cb = jp >> 7, c = jp & 127;
        int jsrc = (c < 64) ? (cb * 64 + c) : (256 + cb * 64 + (c - 64));
        int e = threadIdx.x;
        float w = W[(size_t)e * G3 + jsrc];
        __nv_bfloat16 hi = __float2bfloat16(w);
        float lo = w - __bfloat162float(hi);
        g_Wth[jp * 256 + e] = hi;
        g_Wtl[jp * 256 + e] = __float2bfloat16(lo);
    } else {
        const int b = blockIdx.x - 512;
        const int h = threadIdx.x;
        __shared__ float xs[Ee];
        const int idx = X[b * Tt + (Tt - 1)];
        xs[h] = emb[(size_t)idx * Ee + h];
        __syncthreads();
        float acc = bias[512 + h];
        #pragma unroll 8
        for (int e = 0; e < Ee; e++)
            acc += xs[e] * W[(size_t)e * G3 + 512 + h];
        g_o[b * Hh + h] = 1.0f / (1.0f + expf(-acc));
    }
}

// =====================================================================
// Fused: split-bf16 GEMM (mma.sync + ldmatrix) + activation + in-CTA
// segment scan. CTA = (b, seg) x 64-channel chunk:
//   rows r = b*2048 + t, t in [seg*128, seg*128+128)
//   cols c in [0,128): c<64 -> z_h, c>=64 -> f_h, h = cb*64 + (c%64)
// Epilogue writes only (A, Bc) for the segment. No z/f globals.
// =====================================================================
__global__ __launch_bounds__(256, 2)
void gemm_scan_kernel(const int* __restrict__ X, const float* __restrict__ emb,
                      const float* __restrict__ bias)
{
    extern __shared__ __align__(16) char smem[];
    const int tid  = threadIdx.x;
    const int wid  = tid >> 5, lane = tid & 31;
    const int g    = lane >> 2, tg = lane & 3;
    const int wm   = wid >> 2, wn = wid & 3;        // 2 x 4 warp grid
    const int cb   = blockIdx.x;                    // column block 0..3 (h-chunk)
    const int bseg = blockIdx.y;                    // 0..1023
    const int bat  = bseg >> 4;                     // batch b
    const int seg  = bseg & 15;                     // segment
    const int n0g  = cb * 128;

    int*   sIdx   = (int*)smem;
    float* bias_s = (float*)(smem + 512);
    char*  planes = smem + 1024;
    const uint32_t planes_u32 = smem_u32(planes);

    // per-lane ldmatrix row offsets
    const int aRow = (lane & 7) | (lane & 8);
    const int aK8  = (lane >> 4) * 8;
    const int bN   = (lane & 7) + ((lane & 16) >> 1);
    const int bK8  = (lane & 8);
    const uint32_t aOff = (uint32_t)(wm * 64 + aRow) * ROWB + (uint32_t)aK8 * 2;
    const uint32_t bOff = (uint32_t)(wn * 32 + bN)  * ROWB + (uint32_t)bK8 * 2;

    if (tid < 128) {
        // row tid -> t = seg*128 + tid ; X[b][t] contiguous
        sIdx[tid] = X[bat * Tt + seg * TSEG + tid];
        int c = tid;
        int jg = (c < 64) ? (cb * 64 + c) : (256 + cb * 64 + (c - 64));
        bias_s[tid] = bias[jg];
    }
    __syncthreads();

    float acc[4][4][4];
    #pragma unroll
    for (int mi = 0; mi < 4; mi++)
        #pragma unroll
        for (int ni = 0; ni < 4; ni++)
            #pragma unroll
            for (int c = 0; c < 4; c++) acc[mi][ni][c] = 0.0f;

    // ---- prologue: load stage 0 ----
    {
        #pragma unroll
        for (int i = 0; i < 4; i++) {
            int id = i * 256 + tid;
            int row = id >> 3, f4 = id & 7;
            float4 v = *(const float4*)(emb + (size_t)sIdx[row] * Ee + f4 * 4);
            store_split_row(planes, row, f4 * 4, v);
        }
        #pragma unroll
        for (int i = 0; i < 4; i++) {
            int id = i * 256 + tid;
            int plane = id >> 9, id2 = id & 511;
            int row = id2 >> 2, u4 = id2 & 3;
            const __nv_bfloat16* src =
                (plane ? g_Wtl : g_Wth) + (size_t)(n0g + row) * Ee + u4 * 8;
            uint32_t dst = planes_u32 + (plane ? W_LO_OFF : W_HI_OFF)
                         + (uint32_t)row * ROWB + (uint32_t)u4 * 16;
            cp_async16(dst, src);
        }
        asm volatile("cp.async.commit_group;");
        asm volatile("cp.async.wait_group 0;");
    }
    __syncthreads();

    for (int ch = 0; ch < NCH; ch++) {
        const int cur = ch & 1, nxt = cur ^ 1;

        float4 aPre[4];
        if (ch + 1 < NCH) {
            const int k0 = (ch + 1) * CH;
            #pragma unroll
            for (int i = 0; i < 4; i++) {
                int id = i * 256 + tid;
                int row = id >> 3, f4 = id & 7;
                aPre[i] = *(const float4*)(emb + (size_t)sIdx[row] * Ee + k0 + f4 * 4);
            }
            #pragma unroll
            for (int i = 0; i < 4; i++) {
                int id = i * 256 + tid;
                int plane = id >> 9, id2 = id & 511;
                int row = id2 >> 2, u4 = id2 & 3;
                const __nv_bfloat16* src =
                    (plane ? g_Wtl : g_Wth) + (size_t)(n0g + row) * Ee + k0 + u4 * 8;
                uint32_t dst = planes_u32 + (uint32_t)nxt * STAGE_BYTES
                             + (plane ? W_LO_OFF : W_HI_OFF)
                             + (uint32_t)row * ROWB + (uint32_t)u4 * 16;
                cp_async16(dst, src);
            }
            asm volatile("cp.async.commit_group;");
        }

        const uint32_t sb = planes_u32 + (uint32_t)cur * STAGE_BYTES;
        #pragma unroll
        for (int k16 = 0; k16 < CH; k16 += 16) {
            const uint32_t kb = (uint32_t)k16 * 2;
            uint32_t afr[4][4], bhi[2][4], blo[2][4];
            #pragma unroll
            for (int nn = 0; nn < 2; nn++) {
                ldmx4(bhi[nn], sb + W_HI_OFF + bOff + (uint32_t)nn * 16 * ROWB + kb);
                ldmx4(blo[nn], sb + W_LO_OFF + bOff + (uint32_t)nn * 16 * ROWB + kb);
            }
            #pragma unroll
            for (int mi = 0; mi < 4; mi++)
                ldmx4(afr[mi], sb + A_HI_OFF + aOff + (uint32_t)mi * 16 * ROWB + kb);
            #pragma unroll
            for (int mi = 0; mi < 4; mi++)
                #pragma unroll
                for (int ni = 0; ni < 4; ni++) {
                    mma16816(acc[mi][ni], afr[mi], &bhi[ni >> 1][(ni & 1) * 2]);
                    mma16816(acc[mi][ni], afr[mi], &blo[ni >> 1][(ni & 1) * 2]);
                }
            #pragma unroll
            for (int mi = 0; mi < 4; mi++)
                ldmx4(afr[mi], sb + A_LO_OFF + aOff + (uint32_t)mi * 16 * ROWB + kb);
            #pragma unroll
            for (int mi = 0; mi < 4; mi++)
                #pragma unroll
                for (int ni = 0; ni < 4; ni++)
                    mma16816(acc[mi][ni], afr[mi], &bhi[ni >> 1][(ni & 1) * 2]);
        }

        if (ch + 1 < NCH) {
            char* nb = planes + nxt * STAGE_BYTES;
            #pragma unroll
            for (int i = 0; i < 4; i++) {
                int id = i * 256 + tid;
                int row = id >> 3, f4 = id & 7;
                store_split_row(nb, row, f4 * 4, aPre[i]);
            }
            asm volatile("cp.async.wait_group 0;");
        }
        __syncthreads();
    }

    // ---- epilogue: activation into smem planes ----
    float* zPlane = (float*)planes;                 // [128][68]
    float* fPlane = (float*)(planes + EP_F_OFF);    // [128][68]
    const bool isZ = (wn < 2);
    float* plane = isZ ? zPlane : fPlane;
    #pragma unroll
    for (int mi = 0; mi < 4; mi++) {
        #pragma unroll
        for (int ni = 0; ni < 4; ni++) {
            int lr = wm * 64 + mi * 16 + g;
            int lc = wn * 32 + ni * 8 + tg * 2;
            int h  = isZ ? lc : (lc - 64);
            #pragma unroll
            for (int half = 0; half < 2; half++) {
                float v0 = acc[mi][ni][2 * half + 0] + bias_s[lc];
                float v1 = acc[mi][ni][2 * half + 1] + bias_s[lc + 1];
                float2 o;
                if (isZ) { o.x = tanhf(v0); o.y = tanhf(v1); }
                else {
                    o.x = 1.0f / (1.0f + expf(-v0));
                    o.y = 1.0f / (1.0f + expf(-v1));
                }
                int t = lr + half * 8;
                *(float2*)&plane[t * 68 + h] = o;
            }
        }
    }
    __syncthreads();

    // ---- in-CTA segment scan: 4 windows of 32 t, then combine ----
    {
        const int q = tid >> 6, h = tid & 63;
        float A = 1.0f, Bc = 0.0f;
        const int tq = q * 32;
        #pragma unroll 8
        for (int i = 0; i < 32; i++) {
            float f = fPlane[(tq + i) * 68 + h];
            float z = zPlane[(tq + i) * 68 + h];
            A  = A * f;
            Bc = f * Bc + (1.0f - f) * z;
        }
        float* sA = (float*)(planes + EP_PART_OFF);
        float* sB = sA + 256;
        sA[q * 64 + h] = A;
        sB[q * 64 + h] = Bc;
        __syncthreads();
        if (tid < 64) {
            float At = sA[h], Bt = sB[h];
            #pragma unroll
            for (int q2 = 1; q2 < 4; q2++) {
                float Aq = sA[q2 * 64 + h], Bq = sB[q2 * 64 + h];
                Bt = Bq + Aq * Bt;
                At = At * Aq;
            }
            int hg = cb * 64 + h;
            g_A [(seg * Bb + bat) * Hh + hg] = At;
            g_Bc[(seg * Bb + bat) * Hh + hg] = Bt;
        }
    }
}

// =====================================================================
// Finalize: combine segments -> c_T ; out[b] = (o*c) . W_out + b_out.
// =====================================================================
__global__ __launch_bounds__(256) void finalize_kernel(
    const float* __restrict__ c0, const float* __restrict__ W_out,
    const float* __restrict__ b_out, float* __restrict__ out)
{
    const int b = blockIdx.x;
    const int h = threadIdx.x;
    __shared__ float red[256];

    float c = c0[b * Hh + h];
    #pragma unroll
    for (int s = 0; s < NSEG; s++) {
        float A  = g_A [(s * Bb + b) * Hh + h];
        float Bc = g_Bc[(s * Bb + b) * Hh + h];
        c = A * c + Bc;
    }

    red[h] = (g_o[b * Hh + h] * c) * W_out[h];
    __syncthreads();
    for (int st = 128; st > 0; st >>= 1) {
        if (h < st) red[h] += red[h + st];
        __syncthreads();
    }
    if (h == 0) out[b] = red[0] + b_out[0];
}

// =====================================================================
extern "C" void kernel_launch(void* const* d_in, const int* in_sizes, int n_in,
                              void* d_out, int out_size)
{
    const int*   X     = (const int*)  d_in[0];
    const float* emb   = (const float*)d_in[1];
    const float* W     = (const float*)d_in[2];
    const float* bias  = (const float*)d_in[3];
    const float* c0    = (const float*)d_in[4];
    const float* W_out = (const float*)d_in[5];
    const float* b_out = (const float*)d_in[6];
    float* out = (float*)d_out;

    cudaFuncSetAttribute(gemm_scan_kernel,
                         cudaFuncAttributeMaxDynamicSharedMemorySize, SMEM_BYTES);

    prep_kernel<<<512 + Bb, 256>>>(X, emb, W, bias);
    dim3 g1(4, NSEG * Bb);   // 4 h-chunks x (b, seg)
    gemm_scan_kernel<<<g1, 256, SMEM_BYTES>>>(X, emb, bias);
    finalize_kernel<<<Bb, 256>>>(c0, W_out, b_out, out);
}

// round 12
// speedup vs baseline: 3.4917x; 1.3085x over previous
#include <cuda_runtime.h>
#include <cuda_fp16.h>
#include <math.h>
#include <stdint.h>

// Problem dims (fixed by the reference)
#define Bb   64
#define Tt   2048
#define Ee   256
#define Hh   256
#define G3   768      // 3*H

// Segments: one GEMM row-block (128 rows) == one segment of 128 timesteps
#define NSEG 16
#define TSEG (Tt / NSEG)  // 128

// K chunking for the GEMM
#define CH   32
#define NCH  (Ee / CH)    // 8

// Scratch: per-segment affine composition, o-gate
__device__ float g_A [NSEG * Bb * Hh];
__device__ float g_Bc[NSEG * Bb * Hh];
__device__ float g_o [Bb * Hh];
// Pre-transposed, split-fp16, COLUMN-REMAPPED weights:
//   dest col j' = cb*128 + c ; src gate col = (c<64)? cb*64+c : 256+cb*64+(c-64)
//   g_Wth = fp16(W), g_Wtl = fp16((W - Wth) * 2048)
__device__ __half g_Wth[512 * 256];
__device__ __half g_Wtl[512 * 256];

// ---------------- helpers ----------------
__device__ __forceinline__ uint32_t smem_u32(const void* p) {
    uint32_t a;
    asm("{ .reg .u64 t; cvta.to.shared.u64 t, %1; cvt.u32.u64 %0, t; }"
        : "=r"(a) : "l"(p));
    return a;
}
// m16n8k16 fp16 mma, fp32 accum (baseline sm_80+, OK at compute_103)
__device__ __forceinline__ void mma16816(float* c, const uint32_t* a, const uint32_t* b) {
    asm volatile(
        "mma.sync.aligned.m16n8k16.row.col.f32.f16.f16.f32 "
        "{%0,%1,%2,%3}, {%4,%5,%6,%7}, {%8,%9}, {%0,%1,%2,%3};"
        : "+f"(c[0]), "+f"(c[1]), "+f"(c[2]), "+f"(c[3])
        : "r"(a[0]), "r"(a[1]), "r"(a[2]), "r"(a[3]), "r"(b[0]), "r"(b[1]));
}
__device__ __forceinline__ void ldmx4(uint32_t* r, uint32_t addr) {
    asm volatile("ldmatrix.sync.aligned.m8n8.x4.shared.b16 {%0,%1,%2,%3}, [%4];"
                 : "=r"(r[0]), "=r"(r[1]), "=r"(r[2]), "=r"(r[3]) : "r"(addr));
}
__device__ __forceinline__ void cp_async16(uint32_t dst, const void* src) {
    asm volatile("cp.async.cg.shared.global [%0], [%1], 16;" :: "r"(dst), "l"(src));
}
__device__ __forceinline__ uint32_t hmul2_u32(uint32_t v, __half2 s) {
    __half2 x = *reinterpret_cast<__half2*>(&v);
    x = __hmul2(x, s);
    return *reinterpret_cast<uint32_t*>(&x);
}

// SMEM layout:
//   [0,512)    sIdx (128 ints)
//   [512,1024) bias_s (128 floats)
//   [1024, ...) two pipeline stages; per stage:
//     A (fp16) +0, W_hi +10240, W_lo +20480   (80-byte rows, conflict-free)
// Epilogue reuses the area after [1024):
//   zPlane [128][68]f at +0, fPlane at +34816, partials (2*256 f) at +69632
#define ROWB        80
#define A_OFF       0
#define W_HI_OFF    10240
#define W_LO_OFF    20480
#define STAGE_BYTES 30720
#define EP_F_OFF    34816          // 128*68*4
#define EP_PART_OFF 69632
#define SMEM_BYTES  (1024 + EP_PART_OFF + 2048)   // 72704 (covers both uses)

__device__ __forceinline__ void store_a_row(char* stage, int row, int k, float4 v) {
    __half2 h01 = __floats2half2_rn(v.x, v.y);
    __half2 h23 = __floats2half2_rn(v.z, v.w);
    uint32_t off = (uint32_t)row * ROWB + (uint32_t)k * 2;
    *(uint32_t*)(stage + A_OFF + off)     = *reinterpret_cast<uint32_t*>(&h01);
    *(uint32_t*)(stage + A_OFF + off + 4) = *reinterpret_cast<uint32_t*>(&h23);
}

// =====================================================================
// Prep: coalesced tiled transpose + fp16 split + column-remap of W
// (blocks 0..15, 32 dest cols each); o-gate GEMV at t=T-1 (blocks 16..79).
// =====================================================================
__global__ __launch_bounds__(256) void prep_kernel(
    const int* __restrict__ X, const float* __restrict__ emb,
    const float* __restrict__ W, const float* __restrict__ bias)
{
    __shared__ float tile[32][257];
    const int tid = threadIdx.x;
    if (blockIdx.x < 16) {
        const int j0 = blockIdx.x * 32;          // dest cols [j0, j0+32)
        // src col for dest jp: cb = jp>>7, c = jp&127
        const int cb = j0 >> 7, c0 = j0 & 127;
        const int jsrc0 = (c0 < 64) ? (cb * 64 + c0) : (256 + cb * 64 + (c0 - 64));
        // read 32 src cols x 256 rows, coalesced over j
        const int j = tid & 31, e8 = tid >> 5;
        #pragma unroll 8
        for (int ec = 0; ec < 32; ec++) {
            int e = ec * 8 + e8;
            tile[j][e] = W[(size_t)e * G3 + jsrc0 + j];
        }
        __syncthreads();
        // write transposed, split fp16, coalesced over e
        for (int jl = 0; jl < 32; jl++) {
            float w = tile[jl][tid];
            __half hi = __float2half_rn(w);
            float lo = (w - __half2float(hi)) * 2048.0f;
            size_t o = (size_t)(j0 + jl) * 256 + tid;
            g_Wth[o] = hi;
            g_Wtl[o] = __float2half_rn(lo);
        }
    } else {
        const int b = blockIdx.x - 16;
        const int h = tid;
        __shared__ float xs[Ee];
        const int idx = X[b * Tt + (Tt - 1)];
        xs[h] = emb[(size_t)idx * Ee + h];
        __syncthreads();
        float acc = bias[512 + h];
        #pragma unroll 8
        for (int e = 0; e < Ee; e++)
            acc += xs[e] * W[(size_t)e * G3 + 512 + h];
        g_o[b * Hh + h] = 1.0f / (1.0f + expf(-acc));
    }
}

// =====================================================================
// Fused: 2-pass scaled-fp16 GEMM (mma.sync + ldmatrix) + activation +
// in-CTA segment scan. CTA = (b, seg) x 64-channel chunk:
//   rows r = b*2048 + t, t in [seg*128, seg*128+128)
//   cols c in [0,128): c<64 -> z_h, c>=64 -> f_h, h = cb*64 + (c%64)
// Per k16: ldmatrix A(4) Whi(2) Wlos(2); pass1 A*Whi;
//          scale A regs by 2^-11 (exact); pass2 (A*2^-11)*(Wlo*2048).
// =====================================================================
__global__ __launch_bounds__(256, 2)
void gemm_scan_kernel(const int* __restrict__ X, const float* __restrict__ emb,
                      const float* __restrict__ bias)
{
    extern __shared__ __align__(16) char smem[];
    const int tid  = threadIdx.x;
    const int wid  = tid >> 5, lane = tid & 31;
    const int g    = lane >> 2, tg = lane & 3;
    const int wm   = wid >> 2, wn = wid & 3;        // 2 x 4 warp grid
    const int cb   = blockIdx.x;                    // column block 0..3 (h-chunk)
    const int bseg = blockIdx.y;                    // 0..1023
    const int bat  = bseg >> 4;                     // batch b
    const int seg  = bseg & 15;                     // segment
    const int n0g  = cb * 128;

    int*   sIdx   = (int*)smem;
    float* bias_s = (float*)(smem + 512);
    char*  planes = smem + 1024;
    const uint32_t planes_u32 = smem_u32(planes);
    const __half2 SCL = __float2half2_rn(4.8828125e-4f);   // 2^-11, exact

    // per-lane ldmatrix row offsets
    const int aRow = (lane & 7) | (lane & 8);
    const int aK8  = (lane >> 4) * 8;
    const int bN   = (lane & 7) + ((lane & 16) >> 1);
    const int bK8  = (lane & 8);
    const uint32_t aOff = (uint32_t)(wm * 64 + aRow) * ROWB + (uint32_t)aK8 * 2;
    const uint32_t bOff = (uint32_t)(wn * 32 + bN)  * ROWB + (uint32_t)bK8 * 2;

    if (tid < 128) {
        sIdx[tid] = X[bat * Tt + seg * TSEG + tid];
        int c = tid;
        int jg = (c < 64) ? (cb * 64 + c) : (256 + cb * 64 + (c - 64));
        bias_s[tid] = bias[jg];
    }
    __syncthreads();

    float acc[4][4][4];
    #pragma unroll
    for (int mi = 0; mi < 4; mi++)
        #pragma unroll
        for (int ni = 0; ni < 4; ni++)
            #pragma unroll
            for (int c = 0; c < 4; c++) acc[mi][ni][c] = 0.0f;

    // ---- prologue: load stage 0 ----
    {
        #pragma unroll
        for (int i = 0; i < 4; i++) {
            int id = i * 256 + tid;
            int row = id >> 3, f4 = id & 7;
            float4 v = *(const float4*)(emb + (size_t)sIdx[row] * Ee + f4 * 4);
            store_a_row(planes, row, f4 * 4, v);
        }
        #pragma unroll
        for (int i = 0; i < 4; i++) {
            int id = i * 256 + tid;
            int plane = id >> 9, id2 = id & 511;
            int row = id2 >> 2, u4 = id2 & 3;
            const __half* src =
                (plane ? g_Wtl : g_Wth) + (size_t)(n0g + row) * Ee + u4 * 8;
            uint32_t dst = planes_u32 + (plane ? W_LO_OFF : W_HI_OFF)
                         + (uint32_t)row * ROWB + (uint32_t)u4 * 16;
            cp_async16(dst, src);
        }
        asm volatile("cp.async.commit_group;");
        asm volatile("cp.async.wait_group 0;");
    }
    __syncthreads();

    for (int ch = 0; ch < NCH; ch++) {
        const int cur = ch & 1, nxt = cur ^ 1;

        float4 aPre[4];
        if (ch + 1 < NCH) {
            const int k0 = (ch + 1) * CH;
            #pragma unroll
            for (int i = 0; i < 4; i++) {
                int id = i * 256 + tid;
                int row = id >> 3, f4 = id & 7;
                aPre[i] = *(const float4*)(emb + (size_t)sIdx[row] * Ee + k0 + f4 * 4);
            }
            #pragma unroll
            for (int i = 0; i < 4; i++) {
                int id = i * 256 + tid;
                int plane = id >> 9, id2 = id & 511;
                int row = id2 >> 2, u4 = id2 & 3;
                const __half* src =
                    (plane ? g_Wtl : g_Wth) + (size_t)(n0g + row) * Ee + k0 + u4 * 8;
                uint32_t dst = planes_u32 + (uint32_t)nxt * STAGE_BYTES
                             + (plane ? W_LO_OFF : W_HI_OFF)
                             + (uint32_t)row * ROWB + (uint32_t)u4 * 16;
                cp_async16(dst, src);
            }
            asm volatile("cp.async.commit_group;");
        }

        const uint32_t sb = planes_u32 + (uint32_t)cur * STAGE_BYTES;
        #pragma unroll
        for (int k16 = 0; k16 < CH; k16 += 16) {
            const uint32_t kb = (uint32_t)k16 * 2;
            uint32_t afr[4][4], bhi[2][4], blo[2][4];
            #pragma unroll
            for (int nn = 0; nn < 2; nn++) {
                ldmx4(bhi[nn], sb + W_HI_OFF + bOff + (uint32_t)nn * 16 * ROWB + kb);
                ldmx4(blo[nn], sb + W_LO_OFF + bOff + (uint32_t)nn * 16 * ROWB + kb);
            }
            #pragma unroll
            for (int mi = 0; mi < 4; mi++)
                ldmx4(afr[mi], sb + A_OFF + aOff + (uint32_t)mi * 16 * ROWB + kb);
            // pass 1: A * Whi
            #pragma unroll
            for (int mi = 0; mi < 4; mi++)
                #pragma unroll
                for (int ni = 0; ni < 4; ni++)
                    mma16816(acc[mi][ni], afr[mi], &bhi[ni >> 1][(ni & 1) * 2]);
            // exact rescale A by 2^-11, then pass 2: (A*2^-11) * (Wlo*2048)
            #pragma unroll
            for (int mi = 0; mi < 4; mi++)
                #pragma unroll
                for (int r = 0; r < 4; r++)
                    afr[mi][r] = hmul2_u32(afr[mi][r], SCL);
            #pragma unroll
            for (int mi = 0; mi < 4; mi++)
                #pragma unroll
                for (int ni = 0; ni < 4; ni++)
                    mma16816(acc[mi][ni], afr[mi], &blo[ni >> 1][(ni & 1) * 2]);
        }

        if (ch + 1 < NCH) {
            char* nb = planes + nxt * STAGE_BYTES;
            #pragma unroll
            for (int i = 0; i < 4; i++) {
                int id = i * 256 + tid;
                int row = id >> 3, f4 = id & 7;
                store_a_row(nb, row, f4 * 4, aPre[i]);
            }
            asm volatile("cp.async.wait_group 0;");
        }
        __syncthreads();
    }

    // ---- epilogue: activation into smem planes ----
    float* zPlane = (float*)planes;                 // [128][68]
    float* fPlane = (float*)(planes + EP_F_OFF);    // [128][68]
    const bool isZ = (wn < 2);
    float* plane = isZ ? zPlane : fPlane;
    #pragma unroll
    for (int mi = 0; mi < 4; mi++) {
        #pragma unroll
        for (int ni = 0; ni < 4; ni++) {
            int lr = wm * 64 + mi * 16 + g;
            int lc = wn * 32 + ni * 8 + tg * 2;
            int h  = isZ ? lc : (lc - 64);
            #pragma unroll
            for (int half = 0; half < 2; half++) {
                float v0 = acc[mi][ni][2 * half + 0] + bias_s[lc];
                float v1 = acc[mi][ni][2 * half + 1] + bias_s[lc + 1];
                float2 o;
                if (isZ) { o.x = tanhf(v0); o.y = tanhf(v1); }
                else {
                    o.x = 1.0f / (1.0f + expf(-v0));
                    o.y = 1.0f / (1.0f + expf(-v1));
                }
                int t = lr + half * 8;
                *(float2*)&plane[t * 68 + h] = o;
            }
        }
    }
    __syncthreads();

    // ---- in-CTA segment scan: 4 windows of 32 t, then combine ----
    {
        const int q = tid >> 6, h = tid & 63;
        float A = 1.0f, Bc = 0.0f;
        const int tq = q * 32;
        #pragma unroll 8
        for (int i = 0; i < 32; i++) {
            float f = fPlane[(tq + i) * 68 + h];
            float z = zPlane[(tq + i) * 68 + h];
            A  = A * f;
            Bc = f * Bc + (1.0f - f) * z;
        }
        float* sA = (float*)(planes + EP_PART_OFF);
        float* sB = sA + 256;
        sA[q * 64 + h] = A;
        sB[q * 64 + h] = Bc;
        __syncthreads();
        if (tid < 64) {
            float At = sA[h], Bt = sB[h];
            #pragma unroll
            for (int q2 = 1; q2 < 4; q2++) {
                float Aq = sA[q2 * 64 + h], Bq = sB[q2 * 64 + h];
                Bt = Bq + Aq * Bt;
                At = At * Aq;
            }
            int hg = cb * 64 + h;
            g_A [(seg * Bb + bat) * Hh + hg] = At;
            g_Bc[(seg * Bb + bat) * Hh + hg] = Bt;
        }
    }
}

// =====================================================================
// Finalize: combine segments -> c_T ; out[b] = (o*c) . W_out + b_out.
// =====================================================================
__global__ __launch_bounds__(256) void finalize_kernel(
    const float* __restrict__ c0, const float* __restrict__ W_out,
    const float* __restrict__ b_out, float* __restrict__ out)
{
    const int b = blockIdx.x;
    const int h = threadIdx.x;
    __shared__ float red[256];

    float c = c0[b * Hh + h];
    #pragma unroll
    for (int s = 0; s < NSEG; s++) {
        float A  = g_A [(s * Bb + b) * Hh + h];
        float Bc = g_Bc[(s * Bb + b) * Hh + h];
        c = A * c + Bc;
    }

    red[h] = (g_o[b * Hh + h] * c) * W_out[h];
    __syncthreads();
    for (int st = 128; st > 0; st >>= 1) {
        if (h < st) red[h] += red[h + st];
        __syncthreads();
    }
    if (h == 0) out[b] = red[0] + b_out[0];
}

// =====================================================================
extern "C" void kernel_launch(void* const* d_in, const int* in_sizes, int n_in,
                              void* d_out, int out_size)
{
    const int*   X     = (const int*)  d_in[0];
    const float* emb   = (const float*)d_in[1];
    const float* W     = (const float*)d_in[2];
    const float* bias  = (const float*)d_in[3];
    const float* c0    = (const float*)d_in[4];
    const float* W_out = (const float*)d_in[5];
    const float* b_out = (const float*)d_in[6];
    float* out = (float*)d_out;

    cudaFuncSetAttribute(gemm_scan_kernel,
                         cudaFuncAttributeMaxDynamicSharedMemorySize, SMEM_BYTES);

    prep_kernel<<<16 + Bb, 256>>>(X, emb, W, bias);
    dim3 g1(4, NSEG * Bb);   // 4 h-chunks x (b, seg)
    gemm_scan_kernel<<<g1, 256, SMEM_BYTES>>>(X, emb, bias);
    finalize_kernel<<<Bb, 256>>>(c0, W_out, b_out, out);
}

// round 13
// speedup vs baseline: 9.3815x; 2.6868x over previous
#include <cuda_runtime.h>
#include <cuda_fp16.h>
#include <math.h>
#include <stdint.h>

// Problem dims (fixed by the reference)
#define Bb    64
#define Tt    2048
#define Ee    256
#define Hh    256
#define G3    768      // 3*H
#define VOCAB 32000

// Segments
#define NSEG 16
#define TSEG (Tt / NSEG)  // 128

// K chunking for the GEMM
#define CH   32
#define NCH  (Ee / CH)    // 8

// Table GEMM tiling: 32000 = 250 * 128 row tiles, 4 col blocks
#define NTILES 250
#define NGEMMB (NTILES * 4)   // 1000

// Scratch
__device__ float g_tz[(size_t)VOCAB * Hh];   // activated z table, 32.8 MB
__device__ float g_tf[(size_t)VOCAB * Hh];   // activated f table, 32.8 MB
__device__ float g_A [NSEG * Bb * Hh];
__device__ float g_Bc[NSEG * Bb * Hh];
__device__ float g_o [Bb * Hh];
// Pre-transposed, split-fp16 weights: Wt[j][e] = W[e][j], j in [0,512)
//   g_Wth = fp16(W), g_Wtl = fp16((W - Wth) * 2048)
__device__ __half g_Wth[512 * 256];
__device__ __half g_Wtl[512 * 256];

// ---------------- helpers ----------------
__device__ __forceinline__ uint32_t smem_u32(const void* p) {
    uint32_t a;
    asm("{ .reg .u64 t; cvta.to.shared.u64 t, %1; cvt.u32.u64 %0, t; }"
        : "=r"(a) : "l"(p));
    return a;
}
__device__ __forceinline__ void mma16816(float* c, const uint32_t* a, const uint32_t* b) {
    asm volatile(
        "mma.sync.aligned.m16n8k16.row.col.f32.f16.f16.f32 "
        "{%0,%1,%2,%3}, {%4,%5,%6,%7}, {%8,%9}, {%0,%1,%2,%3};"
        : "+f"(c[0]), "+f"(c[1]), "+f"(c[2]), "+f"(c[3])
        : "r"(a[0]), "r"(a[1]), "r"(a[2]), "r"(a[3]), "r"(b[0]), "r"(b[1]));
}
__device__ __forceinline__ void ldmx4(uint32_t* r, uint32_t addr) {
    asm volatile("ldmatrix.sync.aligned.m8n8.x4.shared.b16 {%0,%1,%2,%3}, [%4];"
                 : "=r"(r[0]), "=r"(r[1]), "=r"(r[2]), "=r"(r[3]) : "r"(addr));
}
__device__ __forceinline__ void cp_async16(uint32_t dst, const void* src) {
    asm volatile("cp.async.cg.shared.global [%0], [%1], 16;" :: "r"(dst), "l"(src));
}
__device__ __forceinline__ uint32_t hmul2_u32(uint32_t v, __half2 s) {
    __half2 x = *reinterpret_cast<__half2*>(&v);
    x = __hmul2(x, s);
    return *reinterpret_cast<uint32_t*>(&x);
}

// SMEM layout for the GEMM kernel:
//   [0,512)    bias_s (128 floats)
//   [512, ...) two pipeline stages; per stage:
//     A (fp16) +0, W_hi +10240, W_lo +20480   (80-byte rows, conflict-free)
#define ROWB        80
#define A_OFF       0
#define W_HI_OFF    10240
#define W_LO_OFF    20480
#define STAGE_BYTES 30720
#define SMEM_BYTES  (1024 + 2 * STAGE_BYTES)   // 62464

__device__ __forceinline__ void store_a_row(char* stage, int row, int k, float4 v) {
    __half2 h01 = __floats2half2_rn(v.x, v.y);
    __half2 h23 = __floats2half2_rn(v.z, v.w);
    uint32_t off = (uint32_t)row * ROWB + (uint32_t)k * 2;
    *(uint32_t*)(stage + A_OFF + off)     = *reinterpret_cast<uint32_t*>(&h01);
    *(uint32_t*)(stage + A_OFF + off + 4) = *reinterpret_cast<uint32_t*>(&h23);
}

// =====================================================================
// Prep: coalesced tiled transpose + fp16 split of W cols [0,512).
// 64 blocks: jg = bx>>2 (32 dest cols), eg = bx&3 (64 e-rows).
// =====================================================================
__global__ __launch_bounds__(256) void prep_w_kernel(const float* __restrict__ W)
{
    __shared__ float tile[32][65];
    const int tid = threadIdx.x;
    const int j0 = (blockIdx.x >> 2) * 32;
    const int e0 = (blockIdx.x & 3) * 64;
    const int j = tid & 31, e8 = tid >> 5;      // 8 e-slices
    #pragma unroll
    for (int ec = 0; ec < 8; ec++) {
        int e = e0 + ec * 8 + e8;
        tile[j][ec * 8 + e8] = W[(size_t)e * G3 + j0 + j];
    }
    __syncthreads();
    const int el = tid & 63;
    #pragma unroll
    for (int it = 0; it < 8; it++) {
        int jl = (tid >> 6) + it * 4;
        float w = tile[jl][el];
        __half hi = __float2half_rn(w);
        float lo = (w - __half2float(hi)) * 2048.0f;
        size_t o = (size_t)(j0 + jl) * 256 + e0 + el;
        g_Wth[o] = hi;
        g_Wtl[o] = __float2half_rn(lo);
    }
}

// =====================================================================
// Vocab-table GEMM: gates for ALL 32000 vocab ids (2-pass scaled fp16)
// + activation into g_tz/g_tf.  Blocks [0,1000): tile = bx>>2, cb = bx&3.
// Blocks [1000,1064): o-gate GEMV at t = T-1 for batch bx-1000.
// =====================================================================
__global__ __launch_bounds__(256, 2)
void table_gemm_kernel(const int* __restrict__ X, const float* __restrict__ emb,
                       const float* __restrict__ W, const float* __restrict__ bias)
{
    if (blockIdx.x >= NGEMMB) {
        // ---- o-gate GEMV ----
        const int b = blockIdx.x - NGEMMB;
        const int h = threadIdx.x;
        __shared__ float xs[Ee];
        const int idx = X[b * Tt + (Tt - 1)];
        xs[h] = emb[(size_t)idx * Ee + h];
        __syncthreads();
        float acc = bias[512 + h];
        #pragma unroll 8
        for (int e = 0; e < Ee; e++)
            acc += xs[e] * W[(size_t)e * G3 + 512 + h];
        g_o[b * Hh + h] = 1.0f / (1.0f + expf(-acc));
        return;
    }

    extern __shared__ __align__(16) char smem[];
    const int tid  = threadIdx.x;
    const int wid  = tid >> 5, lane = tid & 31;
    const int g    = lane >> 2, tg = lane & 3;
    const int wm   = wid >> 2, wn = wid & 3;        // 2 x 4 warp grid
    const int v0   = (blockIdx.x >> 2) * 128;       // vocab row block
    const int cb   = blockIdx.x & 3;                // col block 0..3
    const int n0g  = cb * 128;

    float* bias_s = (float*)smem;
    char*  planes = smem + 1024;
    const uint32_t planes_u32 = smem_u32(planes);
    const __half2 SCL = __float2half2_rn(4.8828125e-4f);   // 2^-11, exact

    // per-lane ldmatrix row offsets
    const int aRow = (lane & 7) | (lane & 8);
    const int aK8  = (lane >> 4) * 8;
    const int bN   = (lane & 7) + ((lane & 16) >> 1);
    const int bK8  = (lane & 8);
    const uint32_t aOff = (uint32_t)(wm * 64 + aRow) * ROWB + (uint32_t)aK8 * 2;
    const uint32_t bOff = (uint32_t)(wn * 32 + bN)  * ROWB + (uint32_t)bK8 * 2;

    if (tid < 128) bias_s[tid] = bias[n0g + tid];

    float acc[4][4][4];
    #pragma unroll
    for (int mi = 0; mi < 4; mi++)
        #pragma unroll
        for (int ni = 0; ni < 4; ni++)
            #pragma unroll
            for (int c = 0; c < 4; c++) acc[mi][ni][c] = 0.0f;

    // ---- prologue: load stage 0 ----
    {
        #pragma unroll
        for (int i = 0; i < 4; i++) {
            int id = i * 256 + tid;
            int row = id >> 3, f4 = id & 7;
            float4 v = *(const float4*)(emb + (size_t)(v0 + row) * Ee + f4 * 4);
            store_a_row(planes, row, f4 * 4, v);
        }
        #pragma unroll
        for (int i = 0; i < 4; i++) {
            int id = i * 256 + tid;
            int plane = id >> 9, id2 = id & 511;
            int row = id2 >> 2, u4 = id2 & 3;
            const __half* src =
                (plane ? g_Wtl : g_Wth) + (size_t)(n0g + row) * Ee + u4 * 8;
            uint32_t dst = planes_u32 + (plane ? W_LO_OFF : W_HI_OFF)
                         + (uint32_t)row * ROWB + (uint32_t)u4 * 16;
            cp_async16(dst, src);
        }
        asm volatile("cp.async.commit_group;");
        asm volatile("cp.async.wait_group 0;");
    }
    __syncthreads();

    for (int ch = 0; ch < NCH; ch++) {
        const int cur = ch & 1, nxt = cur ^ 1;

        float4 aPre[4];
        if (ch + 1 < NCH) {
            const int k0 = (ch + 1) * CH;
            #pragma unroll
            for (int i = 0; i < 4; i++) {
                int id = i * 256 + tid;
                int row = id >> 3, f4 = id & 7;
                aPre[i] = *(const float4*)(emb + (size_t)(v0 + row) * Ee + k0 + f4 * 4);
            }
            #pragma unroll
            for (int i = 0; i < 4; i++) {
                int id = i * 256 + tid;
                int plane = id >> 9, id2 = id & 511;
                int row = id2 >> 2, u4 = id2 & 3;
                const __half* src =
                    (plane ? g_Wtl : g_Wth) + (size_t)(n0g + row) * Ee + k0 + u4 * 8;
                uint32_t dst = planes_u32 + (uint32_t)nxt * STAGE_BYTES
                             + (plane ? W_LO_OFF : W_HI_OFF)
                             + (uint32_t)row * ROWB + (uint32_t)u4 * 16;
                cp_async16(dst, src);
            }
            asm volatile("cp.async.commit_group;");
        }

        const uint32_t sb = planes_u32 + (uint32_t)cur * STAGE_BYTES;
        #pragma unroll
        for (int k16 = 0; k16 < CH; k16 += 16) {
            const uint32_t kb = (uint32_t)k16 * 2;
            uint32_t afr[4][4], bhi[2][4], blo[2][4];
            #pragma unroll
            for (int nn = 0; nn < 2; nn++) {
                ldmx4(bhi[nn], sb + W_HI_OFF + bOff + (uint32_t)nn * 16 * ROWB + kb);
                ldmx4(blo[nn], sb + W_LO_OFF + bOff + (uint32_t)nn * 16 * ROWB + kb);
            }
            #pragma unroll
            for (int mi = 0; mi < 4; mi++)
                ldmx4(afr[mi], sb + A_OFF + aOff + (uint32_t)mi * 16 * ROWB + kb);
            // pass 1: A * Whi
            #pragma unroll
            for (int mi = 0; mi < 4; mi++)
                #pragma unroll
                for (int ni = 0; ni < 4; ni++)
                    mma16816(acc[mi][ni], afr[mi], &bhi[ni >> 1][(ni & 1) * 2]);
            // exact rescale A by 2^-11, then pass 2: (A*2^-11) * (Wlo*2048)
            #pragma unroll
            for (int mi = 0; mi < 4; mi++)
                #pragma unroll
                for (int r = 0; r < 4; r++)
                    afr[mi][r] = hmul2_u32(afr[mi][r], SCL);
            #pragma unroll
            for (int mi = 0; mi < 4; mi++)
                #pragma unroll
                for (int ni = 0; ni < 4; ni++)
                    mma16816(acc[mi][ni], afr[mi], &blo[ni >> 1][(ni & 1) * 2]);
        }

        if (ch + 1 < NCH) {
            char* nb = planes + nxt * STAGE_BYTES;
            #pragma unroll
            for (int i = 0; i < 4; i++) {
                int id = i * 256 + tid;
                int row = id >> 3, f4 = id & 7;
                store_a_row(nb, row, f4 * 4, aPre[i]);
            }
            asm volatile("cp.async.wait_group 0;");
        }
        __syncthreads();
    }

    // ---- epilogue: bias + activation -> vocab tables ----
    const bool isZ = (n0g < 256);
    float* outp = isZ ? g_tz : g_tf;
    const int cbase = isZ ? n0g : (n0g - 256);
    #pragma unroll
    for (int mi = 0; mi < 4; mi++) {
        #pragma unroll
        for (int ni = 0; ni < 4; ni++) {
            int lr = wm * 64 + mi * 16 + g;
            int lc = wn * 32 + ni * 8 + tg * 2;
            #pragma unroll
            for (int half = 0; half < 2; half++) {
                float v0f = acc[mi][ni][2 * half + 0] + bias_s[lc];
                float v1f = acc[mi][ni][2 * half + 1] + bias_s[lc + 1];
                float2 o;
                if (isZ) { o.x = tanhf(v0f); o.y = tanhf(v1f); }
                else {
                    o.x = 1.0f / (1.0f + expf(-v0f));
                    o.y = 1.0f / (1.0f + expf(-v1f));
                }
                size_t v = (size_t)(v0 + lr + half * 8);
                *(float2*)(outp + v * Hh + cbase + lc) = o;
            }
        }
    }
}

// =====================================================================
// Scan: gather gates from the vocab table (L2-resident) + segmented
// affine recurrence. Block = (b, seg); thread = channel h.
// =====================================================================
__global__ __launch_bounds__(256) void scan_kernel(const int* __restrict__ X)
{
    __shared__ int sIdx[TSEG];
    const int h   = threadIdx.x;
    const int bat = blockIdx.x >> 4;
    const int seg = blockIdx.x & 15;

    if (h < TSEG) sIdx[h] = X[bat * Tt + seg * TSEG + h];
    __syncthreads();

    float A = 1.0f, Bc = 0.0f;
    #pragma unroll 8
    for (int t = 0; t < TSEG; t++) {
        size_t row = (size_t)sIdx[t] * Hh + h;
        float f = g_tf[row];
        float z = g_tz[row];
        A  = A * f;
        Bc = f * Bc + (1.0f - f) * z;
    }
    g_A [(seg * Bb + bat) * Hh + h] = A;
    g_Bc[(seg * Bb + bat) * Hh + h] = Bc;
}

// =====================================================================
// Finalize: combine segments -> c_T ; out[b] = (o*c) . W_out + b_out.
// =====================================================================
__global__ __launch_bounds__(256) void finalize_kernel(
    const float* __restrict__ c0, const float* __restrict__ W_out,
    const float* __restrict__ b_out, float* __restrict__ out)
{
    const int b = blockIdx.x;
    const int h = threadIdx.x;
    __shared__ float red[256];

    float c = c0[b * Hh + h];
    #pragma unroll
    for (int s = 0; s < NSEG; s++) {
        float A  = g_A [(s * Bb + b) * Hh + h];
        float Bc = g_Bc[(s * Bb + b) * Hh + h];
        c = A * c + Bc;
    }

    red[h] = (g_o[b * Hh + h] * c) * W_out[h];
    __syncthreads();
    for (int st = 128; st > 0; st >>= 1) {
        if (h < st) red[h] += red[h + st];
        __syncthreads();
    }
    if (h == 0) out[b] = red[0] + b_out[0];
}

// =====================================================================
extern "C" void kernel_launch(void* const* d_in, const int* in_sizes, int n_in,
                              void* d_out, int out_size)
{
    const int*   X     = (const int*)  d_in[0];
    const float* emb   = (const float*)d_in[1];
    const float* W     = (const float*)d_in[2];
    const float* bias  = (const float*)d_in[3];
    const float* c0    = (const float*)d_in[4];
    const float* W_out = (const float*)d_in[5];
    const float* b_out = (const float*)d_in[6];
    float* out = (float*)d_out;

    cudaFuncSetAttribute(table_gemm_kernel,
                         cudaFuncAttributeMaxDynamicSharedMemorySize, SMEM_BYTES);

    prep_w_kernel<<<64, 256>>>(W);
    table_gemm_kernel<<<NGEMMB + Bb, 256, SMEM_BYTES>>>(X, emb, W, bias);
    scan_kernel<<<NSEG * Bb, 256>>>(X);
    finalize_kernel<<<Bb, 256>>>(c0, W_out, b_out, out);
}

// round 14
// speedup vs baseline: 9.8966x; 1.0549x over previous
#include <cuda_runtime.h>
#include <cuda_fp16.h>
#include <math.h>
#include <stdint.h>

// Problem dims (fixed by the reference)
#define Bb    64
#define Tt    2048
#define Ee    256
#define Hh    256
#define G3    768      // 3*H
#define VOCAB 32000

// Segments
#define NSEG 16
#define TSEG (Tt / NSEG)  // 128

// K chunking for the GEMM
#define CH   32
#define NCH  (Ee / CH)    // 8

// Table GEMM tiling: 32000 = 250 * 128 row tiles, 4 col blocks
#define NTILES 250
#define NGEMMB (NTILES * 4)   // 1000

// Scratch
// Packed gate table: word (v,h) = half2(f, u) with u = (1-f)*z.  32.8 MB.
__device__ uint32_t g_t[(size_t)VOCAB * Hh];
__device__ float g_A [NSEG * Bb * Hh];
__device__ float g_Bc[NSEG * Bb * Hh];
__device__ float g_o [Bb * Hh];
// Pre-transposed, split-fp16, COLUMN-REMAPPED weights:
//   dest col j' = cb*128 + c ; src gate col = (c<64)? cb*64+c : 256+cb*64+(c-64)
//   g_Wth = fp16(W), g_Wtl = fp16((W - Wth) * 2048)
__device__ __half g_Wth[512 * 256];
__device__ __half g_Wtl[512 * 256];

// ---------------- helpers ----------------
__device__ __forceinline__ uint32_t smem_u32(const void* p) {
    uint32_t a;
    asm("{ .reg .u64 t; cvta.to.shared.u64 t, %1; cvt.u32.u64 %0, t; }"
        : "=r"(a) : "l"(p));
    return a;
}
__device__ __forceinline__ void mma16816(float* c, const uint32_t* a, const uint32_t* b) {
    asm volatile(
        "mma.sync.aligned.m16n8k16.row.col.f32.f16.f16.f32 "
        "{%0,%1,%2,%3}, {%4,%5,%6,%7}, {%8,%9}, {%0,%1,%2,%3};"
        : "+f"(c[0]), "+f"(c[1]), "+f"(c[2]), "+f"(c[3])
        : "r"(a[0]), "r"(a[1]), "r"(a[2]), "r"(a[3]), "r"(b[0]), "r"(b[1]));
}
__device__ __forceinline__ void ldmx4(uint32_t* r, uint32_t addr) {
    asm volatile("ldmatrix.sync.aligned.m8n8.x4.shared.b16 {%0,%1,%2,%3}, [%4];"
                 : "=r"(r[0]), "=r"(r[1]), "=r"(r[2]), "=r"(r[3]) : "r"(addr));
}
__device__ __forceinline__ void cp_async16(uint32_t dst, const void* src) {
    asm volatile("cp.async.cg.shared.global [%0], [%1], 16;" :: "r"(dst), "l"(src));
}
__device__ __forceinline__ uint32_t hmul2_u32(uint32_t v, __half2 s) {
    __half2 x = *reinterpret_cast<__half2*>(&v);
    x = __hmul2(x, s);
    return *reinterpret_cast<uint32_t*>(&x);
}

// SMEM layout for the GEMM kernel:
//   [0,512)    bias_s (128 floats)
//   [1024, ...) two pipeline stages; per stage:
//     A (fp16) +0, W_hi +10240, W_lo +20480   (80-byte rows, conflict-free)
// Epilogue reuses the stage area: zPlane [128][68]f at +0, fPlane at +34816.
#define ROWB        80
#define A_OFF       0
#define W_HI_OFF    10240
#define W_LO_OFF    20480
#define STAGE_BYTES 30720
#define EP_F_OFF    34816                      // 128*68*4
#define SMEM_BYTES  (1024 + 2 * 34816)         // 70656

__device__ __forceinline__ void store_a_row(char* stage, int row, int k, float4 v) {
    __half2 h01 = __floats2half2_rn(v.x, v.y);
    __half2 h23 = __floats2half2_rn(v.z, v.w);
    uint32_t off = (uint32_t)row * ROWB + (uint32_t)k * 2;
    *(uint32_t*)(stage + A_OFF + off)     = *reinterpret_cast<uint32_t*>(&h01);
    *(uint32_t*)(stage + A_OFF + off + 4) = *reinterpret_cast<uint32_t*>(&h23);
}

// =====================================================================
// Prep: coalesced tiled transpose + fp16 split + COLUMN REMAP of W.
// 64 blocks: dest col group = bx>>2 (32 cols), e-group = bx&3 (64 rows).
// =====================================================================
__global__ __launch_bounds__(256) void prep_w_kernel(const float* __restrict__ W)
{
    __shared__ float tile[32][65];
    const int tid = threadIdx.x;
    const int j0 = (blockIdx.x >> 2) * 32;       // dest cols [j0, j0+32)
    const int e0 = (blockIdx.x & 3) * 64;
    // remap: dest jp -> src gate col (32-col group stays contiguous)
    const int cb = j0 >> 7, c0 = j0 & 127;
    const int jsrc0 = (c0 < 64) ? (cb * 64 + c0) : (256 + cb * 64 + (c0 - 64));
    const int j = tid & 31, e8 = tid >> 5;       // 8 e-slices
    #pragma unroll
    for (int ec = 0; ec < 8; ec++) {
        int e = e0 + ec * 8 + e8;
        tile[j][ec * 8 + e8] = W[(size_t)e * G3 + jsrc0 + j];
    }
    __syncthreads();
    const int el = tid & 63;
    #pragma unroll
    for (int it = 0; it < 8; it++) {
        int jl = (tid >> 6) + it * 4;
        float w = tile[jl][el];
        __half hi = __float2half_rn(w);
        float lo = (w - __half2float(hi)) * 2048.0f;
        size_t o = (size_t)(j0 + jl) * 256 + e0 + el;
        g_Wth[o] = hi;
        g_Wtl[o] = __float2half_rn(lo);
    }
}

// =====================================================================
// Vocab-table GEMM: gates for ALL 32000 vocab ids (2-pass scaled fp16).
// CTA = 128 vocab rows x {z,f} for one 64-channel chunk (remapped cols).
// Epilogue: activation, u = (1-f)*z, pack half2(f,u) -> g_t.
// Blocks [0,1000): tile = bx>>2, cb = bx&3.
// Blocks [1000,1064): o-gate GEMV at t = T-1 for batch bx-1000.
// =====================================================================
__global__ __launch_bounds__(256, 2)
void table_gemm_kernel(const int* __restrict__ X, const float* __restrict__ emb,
                       const float* __restrict__ W, const float* __restrict__ bias)
{
    if (blockIdx.x >= NGEMMB) {
        // ---- o-gate GEMV ----
        const int b = blockIdx.x - NGEMMB;
        const int h = threadIdx.x;
        __shared__ float xs[Ee];
        const int idx = X[b * Tt + (Tt - 1)];
        xs[h] = emb[(size_t)idx * Ee + h];
        __syncthreads();
        float acc = bias[512 + h];
        #pragma unroll 8
        for (int e = 0; e < Ee; e++)
            acc += xs[e] * W[(size_t)e * G3 + 512 + h];
        g_o[b * Hh + h] = 1.0f / (1.0f + expf(-acc));
        return;
    }

    extern __shared__ __align__(16) char smem[];
    const int tid  = threadIdx.x;
    const int wid  = tid >> 5, lane = tid & 31;
    const int g    = lane >> 2, tg = lane & 3;
    const int wm   = wid >> 2, wn = wid & 3;        // 2 x 4 warp grid
    const int v0   = (blockIdx.x >> 2) * 128;       // vocab row block
    const int cb   = blockIdx.x & 3;                // 64-channel chunk
    const int n0g  = cb * 128;

    float* bias_s = (float*)smem;
    char*  planes = smem + 1024;
    const uint32_t planes_u32 = smem_u32(planes);
    const __half2 SCL = __float2half2_rn(4.8828125e-4f);   // 2^-11, exact

    // per-lane ldmatrix row offsets
    const int aRow = (lane & 7) | (lane & 8);
    const int aK8  = (lane >> 4) * 8;
    const int bN   = (lane & 7) + ((lane & 16) >> 1);
    const int bK8  = (lane & 8);
    const uint32_t aOff = (uint32_t)(wm * 64 + aRow) * ROWB + (uint32_t)aK8 * 2;
    const uint32_t bOff = (uint32_t)(wn * 32 + bN)  * ROWB + (uint32_t)bK8 * 2;

    if (tid < 128) {
        int c = tid;
        int jg = (c < 64) ? (cb * 64 + c) : (256 + cb * 64 + (c - 64));
        bias_s[tid] = bias[jg];
    }

    float acc[4][4][4];
    #pragma unroll
    for (int mi = 0; mi < 4; mi++)
        #pragma unroll
        for (int ni = 0; ni < 4; ni++)
            #pragma unroll
            for (int c = 0; c < 4; c++) acc[mi][ni][c] = 0.0f;

    // ---- prologue: load stage 0 ----
    {
        #pragma unroll
        for (int i = 0; i < 4; i++) {
            int id = i * 256 + tid;
            int row = id >> 3, f4 = id & 7;
            float4 v = *(const float4*)(emb + (size_t)(v0 + row) * Ee + f4 * 4);
            store_a_row(planes, row, f4 * 4, v);
        }
        #pragma unroll
        for (int i = 0; i < 4; i++) {
            int id = i * 256 + tid;
            int plane = id >> 9, id2 = id & 511;
            int row = id2 >> 2, u4 = id2 & 3;
            const __half* src =
                (plane ? g_Wtl : g_Wth) + (size_t)(n0g + row) * Ee + u4 * 8;
            uint32_t dst = planes_u32 + (plane ? W_LO_OFF : W_HI_OFF)
                         + (uint32_t)row * ROWB + (uint32_t)u4 * 16;
            cp_async16(dst, src);
        }
        asm volatile("cp.async.commit_group;");
        asm volatile("cp.async.wait_group 0;");
    }
    __syncthreads();

    for (int ch = 0; ch < NCH; ch++) {
        const int cur = ch & 1, nxt = cur ^ 1;

        float4 aPre[4];
        if (ch + 1 < NCH) {
            const int k0 = (ch + 1) * CH;
            #pragma unroll
            for (int i = 0; i < 4; i++) {
                int id = i * 256 + tid;
                int row = id >> 3, f4 = id & 7;
                aPre[i] = *(const float4*)(emb + (size_t)(v0 + row) * Ee + k0 + f4 * 4);
            }
            #pragma unroll
            for (int i = 0; i < 4; i++) {
                int id = i * 256 + tid;
                int plane = id >> 9, id2 = id & 511;
                int row = id2 >> 2, u4 = id2 & 3;
                const __half* src =
                    (plane ? g_Wtl : g_Wth) + (size_t)(n0g + row) * Ee + k0 + u4 * 8;
                uint32_t dst = planes_u32 + (uint32_t)nxt * STAGE_BYTES
                             + (plane ? W_LO_OFF : W_HI_OFF)
                             + (uint32_t)row * ROWB + (uint32_t)u4 * 16;
                cp_async16(dst, src);
            }
            asm volatile("cp.async.commit_group;");
        }

        const uint32_t sb = planes_u32 + (uint32_t)cur * STAGE_BYTES;
        #pragma unroll
        for (int k16 = 0; k16 < CH; k16 += 16) {
            const uint32_t kb = (uint32_t)k16 * 2;
            uint32_t afr[4][4], bhi[2][4], blo[2][4];
            #pragma unroll
            for (int nn = 0; nn < 2; nn++) {
                ldmx4(bhi[nn], sb + W_HI_OFF + bOff + (uint32_t)nn * 16 * ROWB + kb);
                ldmx4(blo[nn], sb + W_LO_OFF + bOff + (uint32_t)nn * 16 * ROWB + kb);
            }
            #pragma unroll
            for (int mi = 0; mi < 4; mi++)
                ldmx4(afr[mi], sb + A_OFF + aOff + (uint32_t)mi * 16 * ROWB + kb);
            // pass 1: A * Whi
            #pragma unroll
            for (int mi = 0; mi < 4; mi++)
                #pragma unroll
                for (int ni = 0; ni < 4; ni++)
                    mma16816(acc[mi][ni], afr[mi], &bhi[ni >> 1][(ni & 1) * 2]);
            // exact rescale A by 2^-11, then pass 2: (A*2^-11) * (Wlo*2048)
            #pragma unroll
            for (int mi = 0; mi < 4; mi++)
                #pragma unroll
                for (int r = 0; r < 4; r++)
                    afr[mi][r] = hmul2_u32(afr[mi][r], SCL);
            #pragma unroll
            for (int mi = 0; mi < 4; mi++)
                #pragma unroll
                for (int ni = 0; ni < 4; ni++)
                    mma16816(acc[mi][ni], afr[mi], &blo[ni >> 1][(ni & 1) * 2]);
        }

        if (ch + 1 < NCH) {
            char* nb = planes + nxt * STAGE_BYTES;
            #pragma unroll
            for (int i = 0; i < 4; i++) {
                int id = i * 256 + tid;
                int row = id >> 3, f4 = id & 7;
                store_a_row(nb, row, f4 * 4, aPre[i]);
            }
            asm volatile("cp.async.wait_group 0;");
        }
        __syncthreads();
    }

    // ---- epilogue: activation into smem planes (z and f for same h-chunk) ----
    float* zPlane = (float*)planes;                 // [128][68]
    float* fPlane = (float*)(planes + EP_F_OFF);    // [128][68]
    const bool isZ = (wn < 2);
    float* plane = isZ ? zPlane : fPlane;
    #pragma unroll
    for (int mi = 0; mi < 4; mi++) {
        #pragma unroll
        for (int ni = 0; ni < 4; ni++) {
            int lr = wm * 64 + mi * 16 + g;
            int lc = wn * 32 + ni * 8 + tg * 2;
            int h  = isZ ? lc : (lc - 64);
            #pragma unroll
            for (int half = 0; half < 2; half++) {
                float v0f = acc[mi][ni][2 * half + 0] + bias_s[lc];
                float v1f = acc[mi][ni][2 * half + 1] + bias_s[lc + 1];
                float2 o;
                if (isZ) { o.x = tanhf(v0f); o.y = tanhf(v1f); }
                else {
                    o.x = 1.0f / (1.0f + expf(-v0f));
                    o.y = 1.0f / (1.0f + expf(-v1f));
                }
                int t = lr + half * 8;
                *(float2*)&plane[t * 68 + h] = o;
            }
        }
    }
    __syncthreads();

    // ---- pack half2(f, u=(1-f)*z) and store to table ----
    #pragma unroll
    for (int i = 0; i < 32; i++) {
        int id  = i * 256 + tid;
        int row = id >> 6, h = id & 63;
        float z = zPlane[row * 68 + h];
        float f = fPlane[row * 68 + h];
        float u = (1.0f - f) * z;
        __half2 p = __floats2half2_rn(f, u);
        g_t[(size_t)(v0 + row) * Hh + cb * 64 + h] = *reinterpret_cast<uint32_t*>(&p);
    }
}

// =====================================================================
// Scan: gather packed gates from the L2-resident table + segmented
// affine recurrence. Block = (b, seg); thread = channel h.
// =====================================================================
__global__ __launch_bounds__(256) void scan_kernel(const int* __restrict__ X)
{
    __shared__ int sIdx[TSEG];
    const int h   = threadIdx.x;
    const int bat = blockIdx.x >> 4;
    const int seg = blockIdx.x & 15;

    if (h < TSEG) sIdx[h] = X[bat * Tt + seg * TSEG + h];
    __syncthreads();

    float A = 1.0f, Bc = 0.0f;
    #pragma unroll 8
    for (int t = 0; t < TSEG; t++) {
        uint32_t w = g_t[(size_t)sIdx[t] * Hh + h];
        __half2 p = *reinterpret_cast<__half2*>(&w);
        float f = __low2float(p);
        float u = __high2float(p);
        A  = A * f;
        Bc = f * Bc + u;
    }
    g_A [(seg * Bb + bat) * Hh + h] = A;
    g_Bc[(seg * Bb + bat) * Hh + h] = Bc;
}

// =====================================================================
// Finalize: combine segments -> c_T ; out[b] = (o*c) . W_out + b_out.
// =====================================================================
__global__ __launch_bounds__(256) void finalize_kernel(
    const float* __restrict__ c0, const float* __restrict__ W_out,
    const float* __restrict__ b_out, float* __restrict__ out)
{
    const int b = blockIdx.x;
    const int h = threadIdx.x;
    __shared__ float red[256];

    float c = c0[b * Hh + h];
    #pragma unroll
    for (int s = 0; s < NSEG; s++) {
        float A  = g_A [(s * Bb + b) * Hh + h];
        float Bc = g_Bc[(s * Bb + b) * Hh + h];
        c = A * c + Bc;
    }

    red[h] = (g_o[b * Hh + h] * c) * W_out[h];
    __syncthreads();
    for (int st = 128; st > 0; st >>= 1) {
        if (h < st) red[h] += red[h + st];
        __syncthreads();
    }
    if (h == 0) out[b] = red[0] + b_out[0];
}

// =====================================================================
extern "C" void kernel_launch(void* const* d_in, const int* in_sizes, int n_in,
                              void* d_out, int out_size)
{
    const int*   X     = (const int*)  d_in[0];
    const float* emb   = (const float*)d_in[1];
    const float* W     = (const float*)d_in[2];
    const float* bias  = (const float*)d_in[3];
    const float* c0    = (const float*)d_in[4];
    const float* W_out = (const float*)d_in[5];
    const float* b_out = (const float*)d_in[6];
    float* out = (float*)d_out;

    cudaFuncSetAttribute(table_gemm_kernel,
                         cudaFuncAttributeMaxDynamicSharedMemorySize, SMEM_BYTES);

    prep_w_kernel<<<64, 256>>>(W);
    table_gemm_kernel<<<NGEMMB + Bb, 256, SMEM_BYTES>>>(X, emb, W, bias);
    scan_kernel<<<NSEG * Bb, 256>>>(X);
    finalize_kernel<<<Bb, 256>>>(c0, W_out, b_out, out);
}

// round 15
// speedup vs baseline: 11.6061x; 1.1727x over previous
#include <cuda_runtime.h>
#include <cuda_fp16.h>
#include <math.h>
#include <stdint.h>

// Problem dims (fixed by the reference)
#define Bb    64
#define Tt    2048
#define Ee    256
#define Hh    256
#define G3    768      // 3*H
#define VOCAB 32000

// Segments
#define NSEG 16
#define TSEG (Tt / NSEG)  // 128

// K chunking for the GEMM
#define CH   32
#define NCH  (Ee / CH)    // 8

// Table GEMM tiling: 32000 = 250 * 128 row tiles, 4 col blocks
#define NTILES 250
#define NGEMMB (NTILES * 4)   // 1000

// Scratch
// Packed gate table: word (v,h) = half2(f, u) with u = (1-f)*z.  32.8 MB.
__device__ uint32_t g_t[(size_t)VOCAB * Hh];
__device__ float g_A [NSEG * Bb * Hh];
__device__ float g_Bc[NSEG * Bb * Hh];
__device__ float g_o [Bb * Hh];
// Pre-transposed fp16, COLUMN-REMAPPED weights:
//   dest col j' = cb*128 + c ; src gate col = (c<64)? cb*64+c : 256+cb*64+(c-64)
__device__ __half g_Wth[512 * 256];

// ---------------- helpers ----------------
__device__ __forceinline__ uint32_t smem_u32(const void* p) {
    uint32_t a;
    asm("{ .reg .u64 t; cvta.to.shared.u64 t, %1; cvt.u32.u64 %0, t; }"
        : "=r"(a) : "l"(p));
    return a;
}
__device__ __forceinline__ void mma16816(float* c, const uint32_t* a, const uint32_t* b) {
    asm volatile(
        "mma.sync.aligned.m16n8k16.row.col.f32.f16.f16.f32 "
        "{%0,%1,%2,%3}, {%4,%5,%6,%7}, {%8,%9}, {%0,%1,%2,%3};"
        : "+f"(c[0]), "+f"(c[1]), "+f"(c[2]), "+f"(c[3])
        : "r"(a[0]), "r"(a[1]), "r"(a[2]), "r"(a[3]), "r"(b[0]), "r"(b[1]));
}
__device__ __forceinline__ void ldmx4(uint32_t* r, uint32_t addr) {
    asm volatile("ldmatrix.sync.aligned.m8n8.x4.shared.b16 {%0,%1,%2,%3}, [%4];"
                 : "=r"(r[0]), "=r"(r[1]), "=r"(r[2]), "=r"(r[3]) : "r"(addr));
}
__device__ __forceinline__ void cp_async16(uint32_t dst, const void* src) {
    asm volatile("cp.async.cg.shared.global [%0], [%1], 16;" :: "r"(dst), "l"(src));
}

// SMEM layout for the GEMM kernel:
//   [0,512)    bias_s (128 floats)
//   [1024, ...) two pipeline stages; per stage:
//     A (fp16) +0, W_hi +10240   (80-byte rows, conflict-free)
// Epilogue reuses the stage area: zPlane [128][68]f at +0, fPlane at +34816.
#define ROWB        80
#define A_OFF       0
#define W_HI_OFF    10240
#define STAGE_BYTES 20480
#define EP_F_OFF    34816                      // 128*68*4
#define SMEM_BYTES  (1024 + 2 * 34816)         // 70656 (covers both uses)

__device__ __forceinline__ void store_a_row(char* stage, int row, int k, float4 v) {
    __half2 h01 = __floats2half2_rn(v.x, v.y);
    __half2 h23 = __floats2half2_rn(v.z, v.w);
    uint32_t off = (uint32_t)row * ROWB + (uint32_t)k * 2;
    *(uint32_t*)(stage + A_OFF + off)     = *reinterpret_cast<uint32_t*>(&h01);
    *(uint32_t*)(stage + A_OFF + off + 4) = *reinterpret_cast<uint32_t*>(&h23);
}

// =====================================================================
// Prep: coalesced tiled transpose + fp16 convert + COLUMN REMAP of W.
// 64 blocks: dest col group = bx>>2 (32 cols), e-group = bx&3 (64 rows).
// =====================================================================
__global__ __launch_bounds__(256) void prep_w_kernel(const float* __restrict__ W)
{
    __shared__ float tile[32][65];
    const int tid = threadIdx.x;
    const int j0 = (blockIdx.x >> 2) * 32;       // dest cols [j0, j0+32)
    const int e0 = (blockIdx.x & 3) * 64;
    const int cb = j0 >> 7, c0 = j0 & 127;
    const int jsrc0 = (c0 < 64) ? (cb * 64 + c0) : (256 + cb * 64 + (c0 - 64));
    const int j = tid & 31, e8 = tid >> 5;       // 8 e-slices
    #pragma unroll
    for (int ec = 0; ec < 8; ec++) {
        int e = e0 + ec * 8 + e8;
        tile[j][ec * 8 + e8] = W[(size_t)e * G3 + jsrc0 + j];
    }
    __syncthreads();
    const int el = tid & 63;
    #pragma unroll
    for (int it = 0; it < 8; it++) {
        int jl = (tid >> 6) + it * 4;
        size_t o = (size_t)(j0 + jl) * 256 + e0 + el;
        g_Wth[o] = __float2half_rn(tile[jl][el]);
    }
}

// =====================================================================
// Vocab-table GEMM: gates for ALL 32000 vocab ids (single-pass fp16).
// CTA = 128 vocab rows x {z,f} for one 64-channel chunk (remapped cols).
// Epilogue: activation, u = (1-f)*z, pack half2(f,u) -> g_t.
// Blocks [0,1000): tile = bx>>2, cb = bx&3.
// Blocks [1000,1064): o-gate GEMV (fp32) at t = T-1 for batch bx-1000.
// =====================================================================
__global__ __launch_bounds__(256, 2)
void table_gemm_kernel(const int* __restrict__ X, const float* __restrict__ emb,
                       const float* __restrict__ W, const float* __restrict__ bias)
{
    if (blockIdx.x >= NGEMMB) {
        // ---- o-gate GEMV ----
        const int b = blockIdx.x - NGEMMB;
        const int h = threadIdx.x;
        __shared__ float xs[Ee];
        const int idx = X[b * Tt + (Tt - 1)];
        xs[h] = emb[(size_t)idx * Ee + h];
        __syncthreads();
        float acc = bias[512 + h];
        #pragma unroll 8
        for (int e = 0; e < Ee; e++)
            acc += xs[e] * W[(size_t)e * G3 + 512 + h];
        g_o[b * Hh + h] = 1.0f / (1.0f + expf(-acc));
        return;
    }

    extern __shared__ __align__(16) char smem[];
    const int tid  = threadIdx.x;
    const int wid  = tid >> 5, lane = tid & 31;
    const int g    = lane >> 2, tg = lane & 3;
    const int wm   = wid >> 2, wn = wid & 3;        // 2 x 4 warp grid
    const int v0   = (blockIdx.x >> 2) * 128;       // vocab row block
    const int cb   = blockIdx.x & 3;                // 64-channel chunk
    const int n0g  = cb * 128;

    float* bias_s = (float*)smem;
    char*  planes = smem + 1024;
    const uint32_t planes_u32 = smem_u32(planes);

    // per-lane ldmatrix row offsets
    const int aRow = (lane & 7) | (lane & 8);
    const int aK8  = (lane >> 4) * 8;
    const int bN   = (lane & 7) + ((lane & 16) >> 1);
    const int bK8  = (lane & 8);
    const uint32_t aOff = (uint32_t)(wm * 64 + aRow) * ROWB + (uint32_t)aK8 * 2;
    const uint32_t bOff = (uint32_t)(wn * 32 + bN)  * ROWB + (uint32_t)bK8 * 2;

    if (tid < 128) {
        int c = tid;
        int jg = (c < 64) ? (cb * 64 + c) : (256 + cb * 64 + (c - 64));
        bias_s[tid] = bias[jg];
    }

    float acc[4][4][4];
    #pragma unroll
    for (int mi = 0; mi < 4; mi++)
        #pragma unroll
        for (int ni = 0; ni < 4; ni++)
            #pragma unroll
            for (int c = 0; c < 4; c++) acc[mi][ni][c] = 0.0f;

    // ---- prologue: load stage 0 ----
    {
        #pragma unroll
        for (int i = 0; i < 4; i++) {
            int id = i * 256 + tid;
            int row = id >> 3, f4 = id & 7;
            float4 v = *(const float4*)(emb + (size_t)(v0 + row) * Ee + f4 * 4);
            store_a_row(planes, row, f4 * 4, v);
        }
        #pragma unroll
        for (int i = 0; i < 2; i++) {
            int id = i * 256 + tid;
            int row = id >> 2, u4 = id & 3;
            const __half* src = g_Wth + (size_t)(n0g + row) * Ee + u4 * 8;
            uint32_t dst = planes_u32 + W_HI_OFF
                         + (uint32_t)row * ROWB + (uint32_t)u4 * 16;
            cp_async16(dst, src);
        }
        asm volatile("cp.async.commit_group;");
        asm volatile("cp.async.wait_group 0;");
    }
    __syncthreads();

    for (int ch = 0; ch < NCH; ch++) {
        const int cur = ch & 1, nxt = cur ^ 1;

        float4 aPre[4];
        if (ch + 1 < NCH) {
            const int k0 = (ch + 1) * CH;
            #pragma unroll
            for (int i = 0; i < 4; i++) {
                int id = i * 256 + tid;
                int row = id >> 3, f4 = id & 7;
                aPre[i] = *(const float4*)(emb + (size_t)(v0 + row) * Ee + k0 + f4 * 4);
            }
            #pragma unroll
            for (int i = 0; i < 2; i++) {
                int id = i * 256 + tid;
                int row = id >> 2, u4 = id & 3;
                const __half* src = g_Wth + (size_t)(n0g + row) * Ee + k0 + u4 * 8;
                uint32_t dst = planes_u32 + (uint32_t)nxt * STAGE_BYTES + W_HI_OFF
                             + (uint32_t)row * ROWB + (uint32_t)u4 * 16;
                cp_async16(dst, src);
            }
            asm volatile("cp.async.commit_group;");
        }

        const uint32_t sb = planes_u32 + (uint32_t)cur * STAGE_BYTES;
        #pragma unroll
        for (int k16 = 0; k16 < CH; k16 += 16) {
            const uint32_t kb = (uint32_t)k16 * 2;
            uint32_t afr[4][4], bhi[2][4];
            #pragma unroll
            for (int nn = 0; nn < 2; nn++)
                ldmx4(bhi[nn], sb + W_HI_OFF + bOff + (uint32_t)nn * 16 * ROWB + kb);
            #pragma unroll
            for (int mi = 0; mi < 4; mi++)
                ldmx4(afr[mi], sb + A_OFF + aOff + (uint32_t)mi * 16 * ROWB + kb);
            #pragma unroll
            for (int mi = 0; mi < 4; mi++)
                #pragma unroll
                for (int ni = 0; ni < 4; ni++)
                    mma16816(acc[mi][ni], afr[mi], &bhi[ni >> 1][(ni & 1) * 2]);
        }

        if (ch + 1 < NCH) {
            char* nb = planes + nxt * STAGE_BYTES;
            #pragma unroll
            for (int i = 0; i < 4; i++) {
                int id = i * 256 + tid;
                int row = id >> 3, f4 = id & 7;
                store_a_row(nb, row, f4 * 4, aPre[i]);
            }
            asm volatile("cp.async.wait_group 0;");
        }
        __syncthreads();
    }

    // ---- epilogue: activation into smem planes (z and f for same h-chunk) ----
    float* zPlane = (float*)planes;                 // [128][68]
    float* fPlane = (float*)(planes + EP_F_OFF);    // [128][68]
    const bool isZ = (wn < 2);
    float* plane = isZ ? zPlane : fPlane;
    #pragma unroll
    for (int mi = 0; mi < 4; mi++) {
        #pragma unroll
        for (int ni = 0; ni < 4; ni++) {
            int lr = wm * 64 + mi * 16 + g;
            int lc = wn * 32 + ni * 8 + tg * 2;
            int h  = isZ ? lc : (lc - 64);
            #pragma unroll
            for (int half = 0; half < 2; half++) {
                float v0f = acc[mi][ni][2 * half + 0] + bias_s[lc];
                float v1f = acc[mi][ni][2 * half + 1] + bias_s[lc + 1];
                float2 o;
                if (isZ) { o.x = tanhf(v0f); o.y = tanhf(v1f); }
                else {
                    o.x = 1.0f / (1.0f + expf(-v0f));
                    o.y = 1.0f / (1.0f + expf(-v1f));
                }
                int t = lr + half * 8;
                *(float2*)&plane[t * 68 + h] = o;
            }
        }
    }
    __syncthreads();

    // ---- pack half2(f, u=(1-f)*z) and store to table ----
    #pragma unroll
    for (int i = 0; i < 32; i++) {
        int id  = i * 256 + tid;
        int row = id >> 6, h = id & 63;
        float z = zPlane[row * 68 + h];
        float f = fPlane[row * 68 + h];
        float u = (1.0f - f) * z;
        __half2 p = __floats2half2_rn(f, u);
        g_t[(size_t)(v0 + row) * Hh + cb * 64 + h] = *reinterpret_cast<uint32_t*>(&p);
    }
}

// =====================================================================
// Scan: gather packed gates from the L2-resident table + segmented
// affine recurrence. Block = (b, seg); thread = channel h.
// =====================================================================
__global__ __launch_bounds__(256) void scan_kernel(const int* __restrict__ X)
{
    __shared__ int sIdx[TSEG];
    const int h   = threadIdx.x;
    const int bat = blockIdx.x >> 4;
    const int seg = blockIdx.x & 15;

    if (h < TSEG) sIdx[h] = X[bat * Tt + seg * TSEG + h];
    __syncthreads();

    float A = 1.0f, Bc = 0.0f;
    #pragma unroll 8
    for (int t = 0; t < TSEG; t++) {
        uint32_t w = g_t[(size_t)sIdx[t] * Hh + h];
        __half2 p = *reinterpret_cast<__half2*>(&w);
        float f = __low2float(p);
        float u = __high2float(p);
        A  = A * f;
        Bc = f * Bc + u;
    }
    g_A [(seg * Bb + bat) * Hh + h] = A;
    g_Bc[(seg * Bb + bat) * Hh + h] = Bc;
}

// =====================================================================
// Finalize: combine segments -> c_T ; out[b] = (o*c) . W_out + b_out.
// =====================================================================
__global__ __launch_bounds__(256) void finalize_kernel(
    const float* __restrict__ c0, const float* __restrict__ W_out,
    const float* __restrict__ b_out, float* __restrict__ out)
{
    const int b = blockIdx.x;
    const int h = threadIdx.x;
    __shared__ float red[256];

    float c = c0[b * Hh + h];
    #pragma unroll
    for (int s = 0; s < NSEG; s++) {
        float A  = g_A [(s * Bb + b) * Hh + h];
        float Bc = g_Bc[(s * Bb + b) * Hh + h];
        c = A * c + Bc;
    }

    red[h] = (g_o[b * Hh + h] * c) * W_out[h];
    __syncthreads();
    for (int st = 128; st > 0; st >>= 1) {
        if (h < st) red[h] += red[h + st];
        __syncthreads();
    }
    if (h == 0) out[b] = red[0] + b_out[0];
}

// =====================================================================
extern "C" void kernel_launch(void* const* d_in, const int* in_sizes, int n_in,
                              void* d_out, int out_size)
{
    const int*   X     = (const int*)  d_in[0];
    const float* emb   = (const float*)d_in[1];
    const float* W     = (const float*)d_in[2];
    const float* bias  = (const float*)d_in[3];
    const float* c0    = (const float*)d_in[4];
    const float* W_out = (const float*)d_in[5];
    const float* b_out = (const float*)d_in[6];
    float* out = (float*)d_out;

    cudaFuncSetAttribute(table_gemm_kernel,
                         cudaFuncAttributeMaxDynamicSharedMemorySize, SMEM_BYTES);

    prep_w_kernel<<<64, 256>>>(W);
    table_gemm_kernel<<<NGEMMB + Bb, 256, SMEM_BYTES>>>(X, emb, W, bias);
    scan_kernel<<<NSEG * Bb, 256>>>(X);
    finalize_kernel<<<Bb, 256>>>(c0, W_out, b_out, out);
}